// round 10
// baseline (speedup 1.0000x reference)
#include <cuda_runtime.h>
#include <cuda_fp16.h>
#include <math.h>
#include <stdint.h>

// Problem dims
#define B     4096
#define F     4096
#define V     1024
#define E     512
#define H     1024
#define L     30
#define G4H   4096
#define KC    1536
#define BOUND 1023
#define LP1   31

// ================= PTX helpers =================
#define CP_ASYNC16(dst, src) asm volatile("cp.async.cg.shared.global [%0], [%1], 16;" :: "r"(dst), "l"(src))
#define CP_COMMIT()          asm volatile("cp.async.commit_group;" ::: "memory")
#define CP_WAIT0()           asm volatile("cp.async.wait_group 0;" ::: "memory")
#define LDMX4(r0,r1,r2,r3, addr) \
    asm volatile("ldmatrix.sync.aligned.m8n8.x4.shared.b16 {%0,%1,%2,%3}, [%4];" \
        : "=r"(r0), "=r"(r1), "=r"(r2), "=r"(r3) : "r"(addr))

__device__ __forceinline__ void mma16816(float* d, const uint32_t* a, uint32_t b0, uint32_t b1)
{
    asm volatile(
        "mma.sync.aligned.m16n8k16.row.col.f32.f16.f16.f32 "
        "{%0,%1,%2,%3}, {%4,%5,%6,%7}, {%8,%9}, {%0,%1,%2,%3};"
        : "+f"(d[0]), "+f"(d[1]), "+f"(d[2]), "+f"(d[3])
        : "r"(a[0]), "r"(a[1]), "r"(a[2]), "r"(a[3]), "r"(b0), "r"(b1));
}

// fp16-accumulator variant (receiver-side cross terms only)
__device__ __forceinline__ void mma16816h(uint32_t* d, const uint32_t* a, uint32_t b0, uint32_t b1)
{
    asm volatile(
        "mma.sync.aligned.m16n8k16.row.col.f16.f16.f16.f16 "
        "{%0,%1}, {%2,%3,%4,%5}, {%6,%7}, {%0,%1};"
        : "+r"(d[0]), "+r"(d[1])
        : "r"(a[0]), "r"(a[1]), "r"(a[2]), "r"(a[3]), "r"(b0), "r"(b1));
}

// ================= device scratch =================
__device__ float g_c[B * H];
__device__ float g_gates[B * G4H];
__device__ int   g_tok[B];
__device__ int   g_sl[B];
__device__ float g_vl[B];
__device__ int   g_m[B * LP1];
__device__ float g_nwc[V];
__device__ float g_r[B * F];
__device__ float g_loss[B];
__device__ float g_acc[B];
__device__ float g_wcnt[V];
__device__ float g_bc[G4H];
__device__ float g_bcR[G4H];
__device__ float g_Ts[V * G4H];
__device__ float g_Tr[V * G4H];
__device__ float4 g_part[B * 8];   // per-(row, vocab-tile) argmax/logsumexp partials

// fp16 split-2 planes (plane1 pre-scaled by 2048)
__device__ __half g_h0a[B * H], g_h1a[B * H];
__device__ __half g_h0b[B * H], g_h1b[B * H];
__device__ __half g_W0p[G4H * KC], g_W1p[G4H * KC];
__device__ __half g_R0p[G4H * KC], g_R1p[G4H * KC];
__device__ __half g_L0p[V * H],  g_L1p[V * H];
__device__ __half g_S0p[H * F],  g_S1p[H * F];
__device__ __half g_A0p[F * H],  g_A1p[F * H];
__device__ __half g_T0p[B * F],  g_T1p[B * F];
__device__ __half g_E0p[V * E],  g_E1p[V * E];
__device__ __half g_F0p[V * E],  g_F1p[V * E];

// ================= merged 3-product HMMA GEMM =================
// mode 0: plain C+bias epilogue.  mode 1: fused LSTM epilogue (Ts gather, c/h update).
// mode 2: fused score-reduction epilogue (argmax + rescaled logsumexp partials).
// F16C=1: cross-term MMAs use fp16 accumulators (receiver-side only; not token-safe).
#define SMPAD       40
#define TILE_BYTES  (128 * SMPAD * 2)
#define STAGE_BYTES (4 * TILE_BYTES)
#define DSM_BYTES   (2 * STAGE_BYTES)     // 81920
#define CS_STRIDE   136

__device__ __forceinline__ void ld_stage(uint32_t sbase, int buf,
    const __half* __restrict__ A0, const __half* __restrict__ A1, int lda, int m0,
    const __half* __restrict__ B0p, const __half* __restrict__ B1p, int ldb, int n0,
    int k0, int tid)
{
    uint32_t dst0 = sbase + buf * STAGE_BYTES;
#pragma unroll
    for (int t = 0; t < 4; t++) {
        const __half* pt = (t == 0) ? A0 : (t == 1) ? A1 : (t == 2) ? B0p : B1p;
        const int ld = (t < 2) ? lda : ldb;
        const int r0g = (t < 2) ? m0 : n0;
#pragma unroll
        for (int i = 0; i < 2; i++) {
            int id = tid + i * 256;
            int r = id >> 2, c = id & 3;
            const __half* src = pt + (size_t)(r0g + r) * ld + k0 + c * 8;
            CP_ASYNC16(dst0 + (uint32_t)(t * TILE_BYTES + (r * SMPAD + c * 8) * 2), src);
        }
    }
}

__device__ __forceinline__ void split2h(float x, __half& o0, __half& o1)
{
    __half h0 = __float2half_rn(x);
    float r = (x - __half2float(h0)) * 2048.f;
    o0 = h0;
    o1 = __float2half_rn(r);
}

template <int F16C>
__global__ void __launch_bounds__(256, 1)
hmma3(const __half* __restrict__ A0, const __half* __restrict__ A1, int lda,
      const __half* __restrict__ B0p, const __half* __restrict__ B1p, int ldb,
      float* __restrict__ C, int ldc, const float* __restrict__ bias, int K,
      int mode,
      const int* __restrict__ toks, int tok_stride,
      const float* __restrict__ Ts,     // mode1: token table; mode2: nwc
      float* __restrict__ cst,          // mode1: cell state; mode2: partials (float4*)
      __half* __restrict__ ho0, __half* __restrict__ ho1)
{
    extern __shared__ __align__(16) char dsm[];
    __shared__ int stok[128];

    const int tid = threadIdx.x;
    const int m0 = blockIdx.y * 128, n0 = blockIdx.x * 128;
    if (mode == 1 && tid < 128) stok[tid] = toks[(size_t)(m0 + tid) * tok_stride];

    const int wid = tid >> 5, lane = tid & 31;
    const int wm = wid & 3, wn = wid >> 2;
    const uint32_t sbase = (uint32_t)__cvta_generic_to_shared(dsm);

    float accM[2][8][4], accC[2][8][4];
    uint32_t accCh[2][8][2];
#pragma unroll
    for (int mt = 0; mt < 2; mt++)
#pragma unroll
        for (int nt = 0; nt < 8; nt++) {
#pragma unroll
            for (int q = 0; q < 4; q++) { accM[mt][nt][q] = 0.f; accC[mt][nt][q] = 0.f; }
            if (F16C) { accCh[mt][nt][0] = 0u; accCh[mt][nt][1] = 0u; }
        }

    const int KT = K >> 5;

    ld_stage(sbase, 0, A0, A1, lda, m0, B0p, B1p, ldb, n0, 0, tid);
    CP_COMMIT();

    for (int kt = 0; kt < KT; kt++) {
        const int cur = kt & 1;
        CP_WAIT0();
        __syncthreads();
        if (kt + 1 < KT) {
            ld_stage(sbase, cur ^ 1, A0, A1, lda, m0, B0p, B1p, ldb, n0, (kt + 1) << 5, tid);
            CP_COMMIT();
        }
        const uint32_t bA0 = sbase + cur * STAGE_BYTES;
        const uint32_t bA1 = bA0 + TILE_BYTES;
        const uint32_t bB0 = bA0 + 2 * TILE_BYTES;
        const uint32_t bB1 = bA0 + 3 * TILE_BYTES;
#pragma unroll
        for (int kh = 0; kh < 2; kh++) {
            const int colh = kh * 16 + ((lane >> 4) & 1) * 8;
            uint32_t a0f[2][4], a1f[2][4];
#pragma unroll
            for (int mt = 0; mt < 2; mt++) {
                int row = wm * 32 + mt * 16 + (lane & 15);
                uint32_t off = (uint32_t)((row * SMPAD + colh) * 2);
                LDMX4(a0f[mt][0], a0f[mt][1], a0f[mt][2], a0f[mt][3], bA0 + off);
                LDMX4(a1f[mt][0], a1f[mt][1], a1f[mt][2], a1f[mt][3], bA1 + off);
            }
#pragma unroll
            for (int bt = 0; bt < 4; bt++) {
                int row = wn * 64 + bt * 16 + (lane & 15);
                uint32_t off = (uint32_t)((row * SMPAD + colh) * 2);
                uint32_t b0f[4], b1f[4];
                LDMX4(b0f[0], b0f[1], b0f[2], b0f[3], bB0 + off);
                LDMX4(b1f[0], b1f[1], b1f[2], b1f[3], bB1 + off);
#pragma unroll
                for (int mt = 0; mt < 2; mt++)
#pragma unroll
                    for (int hi = 0; hi < 2; hi++) {
                        int nt = bt * 2 + hi;
                        mma16816(accM[mt][nt], a0f[mt], b0f[hi], b0f[2 + hi]);
                        if (F16C) {
                            mma16816h(accCh[mt][nt], a0f[mt], b1f[hi], b1f[2 + hi]);
                            mma16816h(accCh[mt][nt], a1f[mt], b0f[hi], b0f[2 + hi]);
                        } else {
                            mma16816(accC[mt][nt], a0f[mt], b1f[hi], b1f[2 + hi]);
                            mma16816(accC[mt][nt], a1f[mt], b0f[hi], b0f[2 + hi]);
                        }
                    }
            }
        }
        if (F16C && (kt & 1)) {
#pragma unroll
            for (int mt = 0; mt < 2; mt++)
#pragma unroll
                for (int nt = 0; nt < 8; nt++) {
                    float2 f01 = __half22float2(*reinterpret_cast<__half2*>(&accCh[mt][nt][0]));
                    float2 f23 = __half22float2(*reinterpret_cast<__half2*>(&accCh[mt][nt][1]));
                    accC[mt][nt][0] += f01.x; accC[mt][nt][1] += f01.y;
                    accC[mt][nt][2] += f23.x; accC[mt][nt][3] += f23.y;
                    accCh[mt][nt][0] = 0u; accCh[mt][nt][1] = 0u;
                }
        }
    }

    const float cs = 1.f / 2048.f;
    const int g = lane >> 2, q2 = (lane & 3) * 2;

    if (mode == 0) {
#pragma unroll
        for (int mt = 0; mt < 2; mt++) {
            int row = m0 + wm * 32 + mt * 16 + g;
#pragma unroll
            for (int nt = 0; nt < 8; nt++) {
                int col = n0 + wn * 64 + nt * 8 + q2;
                float2 bb = *(const float2*)(bias + col);
                float2 o0 = { accM[mt][nt][0] + accC[mt][nt][0] * cs + bb.x,
                              accM[mt][nt][1] + accC[mt][nt][1] * cs + bb.y };
                float2 o1 = { accM[mt][nt][2] + accC[mt][nt][2] * cs + bb.x,
                              accM[mt][nt][3] + accC[mt][nt][3] * cs + bb.y };
                *(float2*)(C + (size_t)row * ldc + col) = o0;
                *(float2*)(C + (size_t)(row + 8) * ldc + col) = o1;
            }
        }
    } else if (mode == 1) {
        __syncthreads();
        float* Cs = (float*)dsm;
#pragma unroll
        for (int mt = 0; mt < 2; mt++) {
            int row = wm * 32 + mt * 16 + g;
#pragma unroll
            for (int nt = 0; nt < 8; nt++) {
                int col = wn * 64 + nt * 8 + q2;
                Cs[row * CS_STRIDE + col]           = accM[mt][nt][0] + accC[mt][nt][0] * cs;
                Cs[row * CS_STRIDE + col + 1]       = accM[mt][nt][1] + accC[mt][nt][1] * cs;
                Cs[(row + 8) * CS_STRIDE + col]     = accM[mt][nt][2] + accC[mt][nt][2] * cs;
                Cs[(row + 8) * CS_STRIDE + col + 1] = accM[mt][nt][3] + accC[mt][nt][3] * cs;
            }
        }
        __syncthreads();
        const int ubase = n0 >> 2;
#pragma unroll
        for (int i = 0; i < 16; i++) {
            int idx = tid + i * 256;
            int b = idx >> 5, u = idx & 31;
            int tok = stok[b];
            float4 g4 = *(float4*)&Cs[b * CS_STRIDE + 4 * u];
            float4 t4 = *(const float4*)(Ts + (size_t)tok * G4H + n0 + 4 * u);
            float gi = g4.x + t4.x, gf = g4.y + t4.y, gg = g4.z + t4.z, go = g4.w + t4.w;
            int bg = m0 + b, j = ubase + u;
            size_t ci = (size_t)bg * H + j;
            float cc = cst[ci];
            float si = 1.f / (1.f + expf(-gi));
            float sf = 1.f / (1.f + expf(-gf));
            float so = 1.f / (1.f + expf(-go));
            float nc = sf * cc + si * tanhf(gg);
            cst[ci] = nc;
            float h = so * tanhf(nc);
            split2h(h, ho0[ci], ho1[ci]);
        }
    } else {
        // mode 2: scores tile -> per-tile argmax + rescaled logsumexp partials
        __syncthreads();
        float* Cs = (float*)dsm;
#pragma unroll
        for (int mt = 0; mt < 2; mt++) {
            int row = wm * 32 + mt * 16 + g;
#pragma unroll
            for (int nt = 0; nt < 8; nt++) {
                int col = wn * 64 + nt * 8 + q2;
                float2 bb = *(const float2*)(bias + n0 + col);
                Cs[row * CS_STRIDE + col]           = accM[mt][nt][0] + accC[mt][nt][0] * cs + bb.x;
                Cs[row * CS_STRIDE + col + 1]       = accM[mt][nt][1] + accC[mt][nt][1] * cs + bb.y;
                Cs[(row + 8) * CS_STRIDE + col]     = accM[mt][nt][2] + accC[mt][nt][2] * cs + bb.x;
                Cs[(row + 8) * CS_STRIDE + col + 1] = accM[mt][nt][3] + accC[mt][nt][3] * cs + bb.y;
            }
        }
        float* snwc = Cs + 128 * CS_STRIDE;
        float4* red = (float4*)(snwc + 128);
        if (tid < 128) snwc[tid] = Ts[n0 + tid];   // Ts = nwc
        __syncthreads();
        int row = tid >> 1, half = tid & 1;
        int c0 = half * 64;
        float bv = -1e30f; int bi = 0; float lm = -1e30f;
        for (int c = c0; c < c0 + 64; c++) {
            float s = Cs[row * CS_STRIDE + c];
            if (s > bv) { bv = s; bi = c; }
            lm = fmaxf(lm, s - snwc[c]);
        }
        float se = 0.f;
        for (int c = c0; c < c0 + 64; c++)
            se += expf(Cs[row * CS_STRIDE + c] - snwc[c] - lm);
        red[tid] = make_float4(bv, __int_as_float(bi), lm, se);
        __syncthreads();
        if (half == 0) {
            float4 a = red[tid], b2 = red[tid + 1];
            float BV = a.x; int BI = __float_as_int(a.y);
            if (b2.x > BV) { BV = b2.x; BI = __float_as_int(b2.y); }   // lower cols first: tie keeps first
            float LM = fmaxf(a.z, b2.z);
            float SE = a.w * expf(a.z - LM) + b2.w * expf(b2.z - LM);
            float4* part = (float4*)cst;
            part[(size_t)(m0 + row) * 8 + blockIdx.x] =
                make_float4(BV, __int_as_float(n0 + BI), LM, SE);
        }
    }
}

// ================= setup / elementwise kernels =================
__global__ void split2_kernel(const float* __restrict__ src, int n,
                              __half* __restrict__ p0, __half* __restrict__ p1)
{
    int i = blockIdx.x * blockDim.x + threadIdx.x;
    if (i < n) split2h(src[i], p0[i], p1[i]);
}

__global__ void build_wc_int(const float* __restrict__ Wih, const float* __restrict__ Whh,
                             __half* __restrict__ p0, __half* __restrict__ p1)
{
    int idx = blockIdx.x * blockDim.x + threadIdx.x;
    if (idx >= G4H * KC) return;
    int n = idx / KC, k = idx % KC;
    int u = n >> 2, gg = n & 3;
    int orig = gg * H + u;
    float w = (k < E) ? Wih[orig * E + k] : Whh[orig * H + (k - E)];
    split2h(w, p0[idx], p1[idx]);
}

__global__ void bias_int(const float* __restrict__ bih, const float* __restrict__ bhh,
                         float* __restrict__ bc)
{
    int n = blockIdx.x * blockDim.x + threadIdx.x;
    if (n >= G4H) return;
    int u = n >> 2, gg = n & 3;
    int orig = gg * H + u;
    bc[n] = bih[orig] + bhh[orig];
}

__global__ void zero_f(float* p, int n)
{
    int i = blockIdx.x * blockDim.x + threadIdx.x;
    if (i < n) p[i] = 0.f;
}

__global__ void zero_h2(__half* p0, __half* p1, int n)
{
    int i = blockIdx.x * blockDim.x + threadIdx.x;
    if (i < n) { p0[i] = __float2half(0.f); p1[i] = __float2half(0.f); }
}

__global__ void build_nwc(const float* __restrict__ wc, float* __restrict__ nwc)
{
    __shared__ float red[1024];
    int t = threadIdx.x;
    float w = wc[t] * (t == BOUND ? 0.1f : 1.0f);
    red[t] = w;
    __syncthreads();
    for (int off = 512; off; off >>= 1) {
        if (t < off) red[t] += red[t + off];
        __syncthreads();
    }
    float denom = red[0];
    nwc[t] = (denom > 0.f) ? (w / denom) : w;
}

__global__ void init_sender(int* tok, int* sl, float* vl, int* m)
{
    int b = blockIdx.x * blockDim.x + threadIdx.x;
    if (b < B) {
        tok[b] = BOUND;
        sl[b] = LP1;
        vl[b] = 0.f;
        m[b * LP1] = BOUND;
    }
}

__global__ void h_split2(const float* __restrict__ hsrc,
                         __half* __restrict__ h0p, __half* __restrict__ h1p)
{
    int idx = blockIdx.x * blockDim.x + threadIdx.x;
    if (idx >= B * H) return;
    split2h(hsrc[idx], h0p[idx], h1p[idx]);
}

// combine 8 per-tile partials -> token, CE, seq-length update
__global__ void score_fin(const float4* __restrict__ part, const float* __restrict__ nwc,
                          int* tok, int* sl, float* vl, int* m, int step)
{
    int b = blockIdx.x * blockDim.x + threadIdx.x;
    if (b >= B) return;
    float4 p[8];
    float BV = -1e30f; int BI = 0; float LM = -1e30f;
#pragma unroll
    for (int t = 0; t < 8; t++) {
        p[t] = part[(size_t)b * 8 + t];
        if (p[t].x > BV) { BV = p[t].x; BI = __float_as_int(p[t].y); }  // ascending tiles: first max wins
        LM = fmaxf(LM, p[t].z);
    }
    float SE = 0.f;
#pragma unroll
    for (int t = 0; t < 8; t++) SE += p[t].w * expf(p[t].z - LM);
    float ce = logf(SE) + LM - (BV - nwc[BI]);
    vl[b] += ce;
    tok[b] = BI;
    if (BI == BOUND && sl[b] == LP1) sl[b] = step + 2;
    m[b * LP1 + step + 1] = BI;
}

__global__ void pad_m(int* __restrict__ m, const int* __restrict__ sl)
{
    int idx = blockIdx.x * blockDim.x + threadIdx.x;
    if (idx >= B * LP1) return;
    int b = idx / LP1, pos = idx % LP1;
    if (pos >= sl[b]) m[idx] = BOUND;
}

__global__ void hist_m(const int* __restrict__ m, float* __restrict__ wcnt)
{
    int idx = blockIdx.x * blockDim.x + threadIdx.x;
    if (idx < B * LP1) atomicAdd(&wcnt[m[idx]], 1.0f);
}

__global__ void hinge_kernel(const float* __restrict__ target, const float* __restrict__ dis,
                             const float* __restrict__ r, const float* __restrict__ vl,
                             float* __restrict__ loss, float* __restrict__ acc)
{
    __shared__ float red[4][257];
    int b = blockIdx.x, t = threadIdx.x;
    const float* rr = r + (size_t)b * F;
    const float* tg = target + (size_t)b * F;
    float s0 = 0.f, s1 = 0.f, s2 = 0.f, s3 = 0.f;
    for (int f = t; f < F; f += 256) {
        float rv = rr[f];
        s0 += tg[f] * rv;
        s1 += dis[(size_t)0 * B * F + (size_t)b * F + f] * rv;
        s2 += dis[(size_t)1 * B * F + (size_t)b * F + f] * rv;
        s3 += dis[(size_t)2 * B * F + (size_t)b * F + f] * rv;
    }
    red[0][t] = s0; red[1][t] = s1; red[2][t] = s2; red[3][t] = s3;
    __syncthreads();
    for (int off = 128; off; off >>= 1) {
        if (t < off) {
#pragma unroll
            for (int q = 0; q < 4; q++) red[q][t] += red[q][t + off];
        }
        __syncthreads();
    }
    if (t == 0) {
        float ts = red[0][0], d0 = red[1][0], d1 = red[2][0], d2 = red[3][0];
        float lo = fmaxf(0.f, 1.f - ts + d0) + fmaxf(0.f, 1.f - ts + d1) + fmaxf(0.f, 1.f - ts + d2);
        loss[b] = lo + 0.1f * vl[b];
        acc[b] = (ts >= d0 && ts >= d1 && ts >= d2) ? 1.f : 0.f;
    }
}

__global__ void finalize(const float* __restrict__ loss, const float* __restrict__ acc, float* __restrict__ out)
{
    __shared__ float rl[1024], ra[1024];
    int t = threadIdx.x;
    float s = 0.f, a = 0.f;
    for (int i = t; i < B; i += 1024) { s += loss[i]; a += acc[i]; }
    rl[t] = s; ra[t] = a;
    __syncthreads();
    for (int off = 512; off; off >>= 1) {
        if (t < off) { rl[t] += rl[t + off]; ra[t] += ra[t + off]; }
        __syncthreads();
    }
    if (t == 0) { out[0] = rl[0] / (float)B; out[1] = ra[0] / (float)B; }
}

__global__ void write_m(const int* __restrict__ m, float* __restrict__ out)
{
    int idx = blockIdx.x * blockDim.x + threadIdx.x;
    if (idx < B * LP1) out[2 + idx] = (float)m[idx];
}

__global__ void write_wc(const float* __restrict__ wcnt, float* __restrict__ out)
{
    int v = blockIdx.x * blockDim.x + threadIdx.x;
    if (v < V) out[2 + B * LP1 + v] = wcnt[v];
}

// ================= launch =================
extern "C" void kernel_launch(void* const* d_in, const int* in_sizes, int n_in,
                              void* d_out, int out_size)
{
    const float* target = (const float*)d_in[0];
    const float* dis    = (const float*)d_in[1];
    const float* wcin   = (const float*)d_in[2];
    const float* emb_s  = (const float*)d_in[3];
    const float* affsW  = (const float*)d_in[4];
    const float* affsb  = (const float*)d_in[5];
    const float* Wih    = (const float*)d_in[6];
    const float* Whh    = (const float*)d_in[7];
    const float* bih    = (const float*)d_in[8];
    const float* bhh    = (const float*)d_in[9];
    const float* lpW    = (const float*)d_in[10];
    const float* lpb    = (const float*)d_in[11];
    const float* emb_r  = (const float*)d_in[12];
    const float* rWih   = (const float*)d_in[13];
    const float* rWhh   = (const float*)d_in[14];
    const float* rbih   = (const float*)d_in[15];
    const float* rbhh   = (const float*)d_in[16];
    const float* affrW  = (const float*)d_in[17];
    const float* affrb  = (const float*)d_in[18];
    float* out = (float*)d_out;

    cudaFuncSetAttribute(hmma3<0>, cudaFuncAttributeMaxDynamicSharedMemorySize, DSM_BYTES);
    cudaFuncSetAttribute(hmma3<1>, cudaFuncAttributeMaxDynamicSharedMemorySize, DSM_BYTES);

    float *p_c, *p_gates, *p_vl, *p_nwc, *p_r, *p_loss, *p_acc, *p_wcnt;
    float *p_bc, *p_bcR, *p_Ts, *p_Tr;
    float4* p_part;
    int *p_tok, *p_sl, *p_m;
    __half *h0[2], *h1[2], *W0p, *W1p, *R0p, *R1p, *L0p, *L1p, *S0p, *S1p, *A0p, *A1p;
    __half *T0p, *T1p, *E0p, *E1p, *Fe0p, *Fe1p;
    cudaGetSymbolAddress((void**)&p_c, g_c);
    cudaGetSymbolAddress((void**)&p_gates, g_gates);
    cudaGetSymbolAddress((void**)&p_vl, g_vl);
    cudaGetSymbolAddress((void**)&p_nwc, g_nwc);
    cudaGetSymbolAddress((void**)&p_r, g_r);
    cudaGetSymbolAddress((void**)&p_loss, g_loss);
    cudaGetSymbolAddress((void**)&p_acc, g_acc);
    cudaGetSymbolAddress((void**)&p_wcnt, g_wcnt);
    cudaGetSymbolAddress((void**)&p_bc, g_bc);
    cudaGetSymbolAddress((void**)&p_bcR, g_bcR);
    cudaGetSymbolAddress((void**)&p_Ts, g_Ts);
    cudaGetSymbolAddress((void**)&p_Tr, g_Tr);
    cudaGetSymbolAddress((void**)&p_part, g_part);
    cudaGetSymbolAddress((void**)&p_tok, g_tok);
    cudaGetSymbolAddress((void**)&p_sl, g_sl);
    cudaGetSymbolAddress((void**)&p_m, g_m);
    cudaGetSymbolAddress((void**)&h0[0], g_h0a); cudaGetSymbolAddress((void**)&h1[0], g_h1a);
    cudaGetSymbolAddress((void**)&h0[1], g_h0b); cudaGetSymbolAddress((void**)&h1[1], g_h1b);
    cudaGetSymbolAddress((void**)&W0p, g_W0p);  cudaGetSymbolAddress((void**)&W1p, g_W1p);
    cudaGetSymbolAddress((void**)&R0p, g_R0p);  cudaGetSymbolAddress((void**)&R1p, g_R1p);
    cudaGetSymbolAddress((void**)&L0p, g_L0p);  cudaGetSymbolAddress((void**)&L1p, g_L1p);
    cudaGetSymbolAddress((void**)&S0p, g_S0p);  cudaGetSymbolAddress((void**)&S1p, g_S1p);
    cudaGetSymbolAddress((void**)&A0p, g_A0p);  cudaGetSymbolAddress((void**)&A1p, g_A1p);
    cudaGetSymbolAddress((void**)&T0p, g_T0p);  cudaGetSymbolAddress((void**)&T1p, g_T1p);
    cudaGetSymbolAddress((void**)&E0p, g_E0p);  cudaGetSymbolAddress((void**)&E1p, g_E1p);
    cudaGetSymbolAddress((void**)&Fe0p, g_F0p); cudaGetSymbolAddress((void**)&Fe1p, g_F1p);

    const int BH = B * H;

    // ---- setup ----
    build_nwc<<<1, 1024>>>(wcin, p_nwc);
    bias_int<<<(G4H + 255) / 256, 256>>>(bih, bhh, p_bc);
    bias_int<<<(G4H + 255) / 256, 256>>>(rbih, rbhh, p_bcR);
    build_wc_int<<<(G4H * KC + 255) / 256, 256>>>(Wih, Whh, W0p, W1p);
    build_wc_int<<<(G4H * KC + 255) / 256, 256>>>(rWih, rWhh, R0p, R1p);
    split2_kernel<<<(V * H + 255) / 256, 256>>>(lpW, V * H, L0p, L1p);
    split2_kernel<<<(H * F + 255) / 256, 256>>>(affsW, H * F, S0p, S1p);
    split2_kernel<<<(F * H + 255) / 256, 256>>>(affrW, F * H, A0p, A1p);
    split2_kernel<<<(B * F + 255) / 256, 256>>>(target, B * F, T0p, T1p);
    split2_kernel<<<(V * E + 255) / 256, 256>>>(emb_s, V * E, E0p, E1p);
    split2_kernel<<<(V * E + 255) / 256, 256>>>(emb_r, V * E, Fe0p, Fe1p);
    zero_f<<<(BH + 255) / 256, 256>>>(p_c, BH);
    init_sender<<<(B + 255) / 256, 256>>>(p_tok, p_sl, p_vl, p_m);

    // ---- token tables (sender table fp32; receiver table may use f16 cross) ----
    hmma3<0><<<dim3(G4H / 128, V / 128), 256, DSM_BYTES>>>(
        E0p, E1p, E, W0p, W1p, KC, p_Ts, G4H, p_bc, E,
        0, nullptr, 0, nullptr, nullptr, nullptr, nullptr);
    hmma3<1><<<dim3(G4H / 128, V / 128), 256, DSM_BYTES>>>(
        Fe0p, Fe1p, E, R0p, R1p, KC, p_Tr, G4H, p_bcR, E,
        0, nullptr, 0, nullptr, nullptr, nullptr, nullptr);

    // ---- h0 = target @ aff_s_W^T + aff_s_b (token-critical: fp32) ----
    hmma3<0><<<dim3(H / 128, B / 128), 256, DSM_BYTES>>>(
        T0p, T1p, F, S0p, S1p, F, p_gates, H, affsb, F,
        0, nullptr, 0, nullptr, nullptr, nullptr, nullptr);
    h_split2<<<(BH + 255) / 256, 256>>>(p_gates, h0[0], h1[0]);

    // ---- sender loop (token-critical: fp32 acc; fused score reduction) ----
    int cur = 0;
    for (int i = 0; i < L; i++) {
        hmma3<0><<<dim3(G4H / 128, B / 128), 256, DSM_BYTES>>>(
            h0[cur], h1[cur], H, W0p + E, W1p + E, KC, nullptr, 0, nullptr, H,
            1, p_tok, 1, p_Ts, p_c, h0[cur ^ 1], h1[cur ^ 1]);
        cur ^= 1;
        hmma3<0><<<dim3(V / 128, B / 128), 256, DSM_BYTES>>>(
            h0[cur], h1[cur], H, L0p, L1p, H, nullptr, 0, lpb, H,
            2, nullptr, 0, p_nwc, (float*)p_part, nullptr, nullptr);
        score_fin<<<B / 256, 256>>>(p_part, p_nwc, p_tok, p_sl, p_vl, p_m, i);
    }

    pad_m<<<(B * LP1 + 255) / 256, 256>>>(p_m, p_sl);
    zero_f<<<(V + 255) / 256, 256>>>(p_wcnt, V);
    hist_m<<<(B * LP1 + 255) / 256, 256>>>(p_m, p_wcnt);

    // ---- receiver (loss-only consumer: fp16-acc cross terms) ----
    zero_f<<<(BH + 255) / 256, 256>>>(p_c, BH);
    zero_h2<<<(BH + 255) / 256, 256>>>(h0[cur], h1[cur], BH);
    for (int t = 0; t < LP1; t++) {
        hmma3<1><<<dim3(G4H / 128, B / 128), 256, DSM_BYTES>>>(
            h0[cur], h1[cur], H, R0p + E, R1p + E, KC, nullptr, 0, nullptr, H,
            1, p_m + t, LP1, p_Tr, p_c, h0[cur ^ 1], h1[cur ^ 1]);
        cur ^= 1;
    }

    // ---- r = hr @ aff_r_W^T + aff_r_b (loss-only: fp16-acc cross) ----
    hmma3<1><<<dim3(F / 128, B / 128), 256, DSM_BYTES>>>(
        h0[cur], h1[cur], H, A0p, A1p, H, p_r, F, affrb, H,
        0, nullptr, 0, nullptr, nullptr, nullptr, nullptr);

    hinge_kernel<<<B, 256>>>(target, dis, p_r, p_vl, p_loss, p_acc);
    finalize<<<1, 1024>>>(p_loss, p_acc, out);
    write_m<<<(B * LP1 + 255) / 256, 256>>>(p_m, out);
    write_wc<<<(V + 255) / 256, 256>>>(p_wcnt, out);
}

// round 11
// speedup vs baseline: 1.4047x; 1.4047x over previous
#include <cuda_runtime.h>
#include <cuda_fp16.h>
#include <math.h>
#include <stdint.h>

// Problem dims
#define B     4096
#define F     4096
#define V     1024
#define E     512
#define H     1024
#define L     30
#define G4H   4096
#define KC    1536
#define BOUND 1023
#define LP1   31

// ================= PTX helpers =================
#define CP_ASYNC16(dst, src) asm volatile("cp.async.cg.shared.global [%0], [%1], 16;" :: "r"(dst), "l"(src))
#define CP_COMMIT()          asm volatile("cp.async.commit_group;" ::: "memory")
#define CP_WAIT0()           asm volatile("cp.async.wait_group 0;" ::: "memory")
#define LDMX4(r0,r1,r2,r3, addr) \
    asm volatile("ldmatrix.sync.aligned.m8n8.x4.shared.b16 {%0,%1,%2,%3}, [%4];" \
        : "=r"(r0), "=r"(r1), "=r"(r2), "=r"(r3) : "r"(addr))

__device__ __forceinline__ void mma16816(float* d, const uint32_t* a, uint32_t b0, uint32_t b1)
{
    asm volatile(
        "mma.sync.aligned.m16n8k16.row.col.f32.f16.f16.f32 "
        "{%0,%1,%2,%3}, {%4,%5,%6,%7}, {%8,%9}, {%0,%1,%2,%3};"
        : "+f"(d[0]), "+f"(d[1]), "+f"(d[2]), "+f"(d[3])
        : "r"(a[0]), "r"(a[1]), "r"(a[2]), "r"(a[3]), "r"(b0), "r"(b1));
}

// ================= device scratch =================
__device__ float g_c[B * H];
__device__ float g_gates[B * G4H];
__device__ float g_scores[B * V];
__device__ int   g_tok[B];
__device__ int   g_sl[B];
__device__ float g_vl[B];
__device__ int   g_m[B * LP1];
__device__ float g_nwc[V];
__device__ float g_r[B * F];
__device__ float g_loss[B];
__device__ float g_acc[B];
__device__ float g_wcnt[V];
__device__ float g_bc[G4H];        // interleaved combined bias (sender)
__device__ float g_bcR[G4H];       // interleaved combined bias (receiver)
__device__ float g_Ts[V * G4H];    // emb_s @ Wc^T + bias (interleaved cols)
__device__ float g_Tr[V * G4H];    // emb_r @ Rc^T + bias

// fp16 split-2 planes (plane1 pre-scaled by 2048)
__device__ __half g_h0a[B * H], g_h1a[B * H];
__device__ __half g_h0b[B * H], g_h1b[B * H];
__device__ __half g_W0p[G4H * KC], g_W1p[G4H * KC];
__device__ __half g_R0p[G4H * KC], g_R1p[G4H * KC];
__device__ __half g_L0p[V * H],  g_L1p[V * H];
__device__ __half g_S0p[H * F],  g_S1p[H * F];
__device__ __half g_A0p[F * H],  g_A1p[F * H];
__device__ __half g_T0p[B * F],  g_T1p[B * F];
__device__ __half g_E0p[V * E],  g_E1p[V * E];
__device__ __half g_F0p[V * E],  g_F1p[V * E];

// ================= merged HMMA GEMM =================
// NP=3: split-2 fp16 with compensated cross terms (token-critical, fp32-equivalent).
// NP=1: single-pass plain fp16 (receiver/loss-only path; ~1e-3 relative).
// mode 0: plain C+bias epilogue.  mode 1: fused LSTM epilogue (Ts gather, c/h update).
#define SMPAD       40
#define TILE_BYTES  (128 * SMPAD * 2)
#define STAGE_BYTES (4 * TILE_BYTES)
#define DSM_BYTES   (2 * STAGE_BYTES)     // 81920
#define CS_STRIDE   136

template <int NP>
__device__ __forceinline__ void ld_stage(uint32_t sbase, int buf,
    const __half* __restrict__ A0, const __half* __restrict__ A1, int lda, int m0,
    const __half* __restrict__ B0p, const __half* __restrict__ B1p, int ldb, int n0,
    int k0, int tid)
{
    uint32_t dst0 = sbase + buf * STAGE_BYTES;
#pragma unroll
    for (int t = 0; t < 4; t++) {
        if (NP == 1 && (t == 1 || t == 3)) continue;   // single-pass: only A0, B0
        const __half* pt = (t == 0) ? A0 : (t == 1) ? A1 : (t == 2) ? B0p : B1p;
        const int ld = (t < 2) ? lda : ldb;
        const int r0g = (t < 2) ? m0 : n0;
#pragma unroll
        for (int i = 0; i < 2; i++) {
            int id = tid + i * 256;
            int r = id >> 2, c = id & 3;
            const __half* src = pt + (size_t)(r0g + r) * ld + k0 + c * 8;
            CP_ASYNC16(dst0 + (uint32_t)(t * TILE_BYTES + (r * SMPAD + c * 8) * 2), src);
        }
    }
}

__device__ __forceinline__ void split2h(float x, __half& o0, __half& o1)
{
    __half h0 = __float2half_rn(x);
    float r = (x - __half2float(h0)) * 2048.f;
    o0 = h0;
    o1 = __float2half_rn(r);
}

template <int NP>
__global__ void __launch_bounds__(256, 1)
hmma3(const __half* __restrict__ A0, const __half* __restrict__ A1, int lda,
      const __half* __restrict__ B0p, const __half* __restrict__ B1p, int ldb,
      float* __restrict__ C, int ldc, const float* __restrict__ bias, int K,
      int mode,
      const int* __restrict__ toks, int tok_stride,
      const float* __restrict__ Ts,
      float* __restrict__ cst, __half* __restrict__ ho0, __half* __restrict__ ho1)
{
    extern __shared__ __align__(16) char dsm[];
    __shared__ int stok[128];

    const int tid = threadIdx.x;
    const int m0 = blockIdx.y * 128, n0 = blockIdx.x * 128;
    if (mode == 1 && tid < 128) stok[tid] = toks[(size_t)(m0 + tid) * tok_stride];

    const int wid = tid >> 5, lane = tid & 31;
    const int wm = wid & 3, wn = wid >> 2;
    const uint32_t sbase = (uint32_t)__cvta_generic_to_shared(dsm);

    float accM[2][8][4], accC[2][8][4];
#pragma unroll
    for (int mt = 0; mt < 2; mt++)
#pragma unroll
        for (int nt = 0; nt < 8; nt++)
#pragma unroll
            for (int q = 0; q < 4; q++) { accM[mt][nt][q] = 0.f; accC[mt][nt][q] = 0.f; }

    const int KT = K >> 5;

    ld_stage<NP>(sbase, 0, A0, A1, lda, m0, B0p, B1p, ldb, n0, 0, tid);
    CP_COMMIT();

    for (int kt = 0; kt < KT; kt++) {
        const int cur = kt & 1;
        CP_WAIT0();
        __syncthreads();
        if (kt + 1 < KT) {
            ld_stage<NP>(sbase, cur ^ 1, A0, A1, lda, m0, B0p, B1p, ldb, n0, (kt + 1) << 5, tid);
            CP_COMMIT();
        }
        const uint32_t bA0 = sbase + cur * STAGE_BYTES;
        const uint32_t bA1 = bA0 + TILE_BYTES;
        const uint32_t bB0 = bA0 + 2 * TILE_BYTES;
        const uint32_t bB1 = bA0 + 3 * TILE_BYTES;
#pragma unroll
        for (int kh = 0; kh < 2; kh++) {
            const int colh = kh * 16 + ((lane >> 4) & 1) * 8;
            uint32_t a0f[2][4], a1f[2][4];
#pragma unroll
            for (int mt = 0; mt < 2; mt++) {
                int row = wm * 32 + mt * 16 + (lane & 15);
                uint32_t off = (uint32_t)((row * SMPAD + colh) * 2);
                LDMX4(a0f[mt][0], a0f[mt][1], a0f[mt][2], a0f[mt][3], bA0 + off);
                if (NP == 3)
                    LDMX4(a1f[mt][0], a1f[mt][1], a1f[mt][2], a1f[mt][3], bA1 + off);
            }
#pragma unroll
            for (int bt = 0; bt < 4; bt++) {
                int row = wn * 64 + bt * 16 + (lane & 15);
                uint32_t off = (uint32_t)((row * SMPAD + colh) * 2);
                uint32_t b0f[4], b1f[4];
                LDMX4(b0f[0], b0f[1], b0f[2], b0f[3], bB0 + off);
                if (NP == 3)
                    LDMX4(b1f[0], b1f[1], b1f[2], b1f[3], bB1 + off);
#pragma unroll
                for (int mt = 0; mt < 2; mt++)
#pragma unroll
                    for (int hi = 0; hi < 2; hi++) {
                        int nt = bt * 2 + hi;
                        mma16816(accM[mt][nt], a0f[mt], b0f[hi], b0f[2 + hi]);
                        if (NP == 3) {
                            mma16816(accC[mt][nt], a0f[mt], b1f[hi], b1f[2 + hi]);
                            mma16816(accC[mt][nt], a1f[mt], b0f[hi], b0f[2 + hi]);
                        }
                    }
            }
        }
    }

    const float cs = 1.f / 2048.f;
    const int g = lane >> 2, q2 = (lane & 3) * 2;

    if (mode == 0) {
#pragma unroll
        for (int mt = 0; mt < 2; mt++) {
            int row = m0 + wm * 32 + mt * 16 + g;
#pragma unroll
            for (int nt = 0; nt < 8; nt++) {
                int col = n0 + wn * 64 + nt * 8 + q2;
                float2 bb = *(const float2*)(bias + col);
                float2 o0 = { accM[mt][nt][0] + accC[mt][nt][0] * cs + bb.x,
                              accM[mt][nt][1] + accC[mt][nt][1] * cs + bb.y };
                float2 o1 = { accM[mt][nt][2] + accC[mt][nt][2] * cs + bb.x,
                              accM[mt][nt][3] + accC[mt][nt][3] * cs + bb.y };
                *(float2*)(C + (size_t)row * ldc + col) = o0;
                *(float2*)(C + (size_t)(row + 8) * ldc + col) = o1;
            }
        }
    } else {
        __syncthreads();
        float* Cs = (float*)dsm;
#pragma unroll
        for (int mt = 0; mt < 2; mt++) {
            int row = wm * 32 + mt * 16 + g;
#pragma unroll
            for (int nt = 0; nt < 8; nt++) {
                int col = wn * 64 + nt * 8 + q2;
                Cs[row * CS_STRIDE + col]           = accM[mt][nt][0] + accC[mt][nt][0] * cs;
                Cs[row * CS_STRIDE + col + 1]       = accM[mt][nt][1] + accC[mt][nt][1] * cs;
                Cs[(row + 8) * CS_STRIDE + col]     = accM[mt][nt][2] + accC[mt][nt][2] * cs;
                Cs[(row + 8) * CS_STRIDE + col + 1] = accM[mt][nt][3] + accC[mt][nt][3] * cs;
            }
        }
        __syncthreads();
        const int ubase = n0 >> 2;
#pragma unroll
        for (int i = 0; i < 16; i++) {
            int idx = tid + i * 256;
            int b = idx >> 5, u = idx & 31;
            int tok = stok[b];
            float4 g4 = *(float4*)&Cs[b * CS_STRIDE + 4 * u];
            float4 t4 = *(const float4*)(Ts + (size_t)tok * G4H + n0 + 4 * u);
            float gi = g4.x + t4.x, gf = g4.y + t4.y, gg = g4.z + t4.z, go = g4.w + t4.w;
            int bg = m0 + b, j = ubase + u;
            size_t ci = (size_t)bg * H + j;
            float cc = cst[ci];
            float si = 1.f / (1.f + expf(-gi));
            float sf = 1.f / (1.f + expf(-gf));
            float so = 1.f / (1.f + expf(-go));
            float nc = sf * cc + si * tanhf(gg);
            cst[ci] = nc;
            float h = so * tanhf(nc);
            split2h(h, ho0[ci], ho1[ci]);
        }
    }
}

// ================= setup / elementwise kernels =================
__global__ void split2_kernel(const float* __restrict__ src, int n,
                              __half* __restrict__ p0, __half* __restrict__ p1)
{
    int i = blockIdx.x * blockDim.x + threadIdx.x;
    if (i < n) split2h(src[i], p0[i], p1[i]);
}

__global__ void build_wc_int(const float* __restrict__ Wih, const float* __restrict__ Whh,
                             __half* __restrict__ p0, __half* __restrict__ p1)
{
    int idx = blockIdx.x * blockDim.x + threadIdx.x;
    if (idx >= G4H * KC) return;
    int n = idx / KC, k = idx % KC;
    int u = n >> 2, gg = n & 3;
    int orig = gg * H + u;
    float w = (k < E) ? Wih[orig * E + k] : Whh[orig * H + (k - E)];
    split2h(w, p0[idx], p1[idx]);
}

__global__ void bias_int(const float* __restrict__ bih, const float* __restrict__ bhh,
                         float* __restrict__ bc)
{
    int n = blockIdx.x * blockDim.x + threadIdx.x;
    if (n >= G4H) return;
    int u = n >> 2, gg = n & 3;
    int orig = gg * H + u;
    bc[n] = bih[orig] + bhh[orig];
}

__global__ void zero_f(float* p, int n)
{
    int i = blockIdx.x * blockDim.x + threadIdx.x;
    if (i < n) p[i] = 0.f;
}

__global__ void zero_h2(__half* p0, __half* p1, int n)
{
    int i = blockIdx.x * blockDim.x + threadIdx.x;
    if (i < n) { p0[i] = __float2half(0.f); p1[i] = __float2half(0.f); }
}

__global__ void build_nwc(const float* __restrict__ wc, float* __restrict__ nwc)
{
    __shared__ float red[1024];
    int t = threadIdx.x;
    float w = wc[t] * (t == BOUND ? 0.1f : 1.0f);
    red[t] = w;
    __syncthreads();
    for (int off = 512; off; off >>= 1) {
        if (t < off) red[t] += red[t + off];
        __syncthreads();
    }
    float denom = red[0];
    nwc[t] = (denom > 0.f) ? (w / denom) : w;
}

__global__ void init_sender(int* tok, int* sl, float* vl, int* m)
{
    int b = blockIdx.x * blockDim.x + threadIdx.x;
    if (b < B) {
        tok[b] = BOUND;
        sl[b] = LP1;
        vl[b] = 0.f;
        m[b * LP1] = BOUND;
    }
}

__global__ void h_split2(const float* __restrict__ hsrc,
                         __half* __restrict__ h0p, __half* __restrict__ h1p)
{
    int idx = blockIdx.x * blockDim.x + threadIdx.x;
    if (idx >= B * H) return;
    split2h(hsrc[idx], h0p[idx], h1p[idx]);
}

__global__ void score_step(const float* __restrict__ scores, const float* __restrict__ nwc,
                           int* tok, int* sl, float* vl, int* m, int step)
{
    __shared__ float sBest[256];
    __shared__ int   sIdx[256];
    __shared__ float sLM[256];
    __shared__ float sSum[256];
    int b = blockIdx.x, tid = threadIdx.x;
    const float* srow = scores + (size_t)b * V;

    float best = -1e30f; int bidx = 0; float lmax = -1e30f;
    for (int v = tid; v < V; v += 256) {
        float s = srow[v];
        if (s > best) { best = s; bidx = v; }
        float lg = s - nwc[v];
        lmax = fmaxf(lmax, lg);
    }
    sBest[tid] = best; sIdx[tid] = bidx; sLM[tid] = lmax;
    __syncthreads();
    for (int off = 128; off; off >>= 1) {
        if (tid < off) {
            float ob = sBest[tid + off]; int oi = sIdx[tid + off];
            if (ob > sBest[tid] || (ob == sBest[tid] && oi < sIdx[tid])) { sBest[tid] = ob; sIdx[tid] = oi; }
            sLM[tid] = fmaxf(sLM[tid], sLM[tid + off]);
        }
        __syncthreads();
    }
    float LM = sLM[0];
    int t = sIdx[0];
    __syncthreads();

    float ssum = 0.f;
    for (int v = tid; v < V; v += 256) ssum += expf(srow[v] - nwc[v] - LM);
    sSum[tid] = ssum;
    __syncthreads();
    for (int off = 128; off; off >>= 1) {
        if (tid < off) sSum[tid] += sSum[tid + off];
        __syncthreads();
    }
    if (tid == 0) {
        float ce = logf(sSum[0]) + LM - (srow[t] - nwc[t]);
        vl[b] += ce;
        tok[b] = t;
        if (t == BOUND && sl[b] == LP1) sl[b] = step + 2;
        m[b * LP1 + step + 1] = t;
    }
}

__global__ void pad_m(int* __restrict__ m, const int* __restrict__ sl)
{
    int idx = blockIdx.x * blockDim.x + threadIdx.x;
    if (idx >= B * LP1) return;
    int b = idx / LP1, pos = idx % LP1;
    if (pos >= sl[b]) m[idx] = BOUND;
}

__global__ void hist_m(const int* __restrict__ m, float* __restrict__ wcnt)
{
    int idx = blockIdx.x * blockDim.x + threadIdx.x;
    if (idx < B * LP1) atomicAdd(&wcnt[m[idx]], 1.0f);
}

__global__ void hinge_kernel(const float* __restrict__ target, const float* __restrict__ dis,
                             const float* __restrict__ r, const float* __restrict__ vl,
                             float* __restrict__ loss, float* __restrict__ acc)
{
    __shared__ float red[4][257];
    int b = blockIdx.x, t = threadIdx.x;
    const float* rr = r + (size_t)b * F;
    const float* tg = target + (size_t)b * F;
    float s0 = 0.f, s1 = 0.f, s2 = 0.f, s3 = 0.f;
    for (int f = t; f < F; f += 256) {
        float rv = rr[f];
        s0 += tg[f] * rv;
        s1 += dis[(size_t)0 * B * F + (size_t)b * F + f] * rv;
        s2 += dis[(size_t)1 * B * F + (size_t)b * F + f] * rv;
        s3 += dis[(size_t)2 * B * F + (size_t)b * F + f] * rv;
    }
    red[0][t] = s0; red[1][t] = s1; red[2][t] = s2; red[3][t] = s3;
    __syncthreads();
    for (int off = 128; off; off >>= 1) {
        if (t < off) {
#pragma unroll
            for (int q = 0; q < 4; q++) red[q][t] += red[q][t + off];
        }
        __syncthreads();
    }
    if (t == 0) {
        float ts = red[0][0], d0 = red[1][0], d1 = red[2][0], d2 = red[3][0];
        float lo = fmaxf(0.f, 1.f - ts + d0) + fmaxf(0.f, 1.f - ts + d1) + fmaxf(0.f, 1.f - ts + d2);
        loss[b] = lo + 0.1f * vl[b];
        acc[b] = (ts >= d0 && ts >= d1 && ts >= d2) ? 1.f : 0.f;
    }
}

__global__ void finalize(const float* __restrict__ loss, const float* __restrict__ acc, float* __restrict__ out)
{
    __shared__ float rl[1024], ra[1024];
    int t = threadIdx.x;
    float s = 0.f, a = 0.f;
    for (int i = t; i < B; i += 1024) { s += loss[i]; a += acc[i]; }
    rl[t] = s; ra[t] = a;
    __syncthreads();
    for (int off = 512; off; off >>= 1) {
        if (t < off) { rl[t] += rl[t + off]; ra[t] += ra[t + off]; }
        __syncthreads();
    }
    if (t == 0) { out[0] = rl[0] / (float)B; out[1] = ra[0] / (float)B; }
}

__global__ void write_m(const int* __restrict__ m, float* __restrict__ out)
{
    int idx = blockIdx.x * blockDim.x + threadIdx.x;
    if (idx < B * LP1) out[2 + idx] = (float)m[idx];
}

__global__ void write_wc(const float* __restrict__ wcnt, float* __restrict__ out)
{
    int v = blockIdx.x * blockDim.x + threadIdx.x;
    if (v < V) out[2 + B * LP1 + v] = wcnt[v];
}

// ================= launch =================
extern "C" void kernel_launch(void* const* d_in, const int* in_sizes, int n_in,
                              void* d_out, int out_size)
{
    const float* target = (const float*)d_in[0];
    const float* dis    = (const float*)d_in[1];
    const float* wcin   = (const float*)d_in[2];
    const float* emb_s  = (const float*)d_in[3];
    const float* affsW  = (const float*)d_in[4];
    const float* affsb  = (const float*)d_in[5];
    const float* Wih    = (const float*)d_in[6];
    const float* Whh    = (const float*)d_in[7];
    const float* bih    = (const float*)d_in[8];
    const float* bhh    = (const float*)d_in[9];
    const float* lpW    = (const float*)d_in[10];
    const float* lpb    = (const float*)d_in[11];
    const float* emb_r  = (const float*)d_in[12];
    const float* rWih   = (const float*)d_in[13];
    const float* rWhh   = (const float*)d_in[14];
    const float* rbih   = (const float*)d_in[15];
    const float* rbhh   = (const float*)d_in[16];
    const float* affrW  = (const float*)d_in[17];
    const float* affrb  = (const float*)d_in[18];
    float* out = (float*)d_out;

    cudaFuncSetAttribute(hmma3<3>, cudaFuncAttributeMaxDynamicSharedMemorySize, DSM_BYTES);
    cudaFuncSetAttribute(hmma3<1>, cudaFuncAttributeMaxDynamicSharedMemorySize, DSM_BYTES);

    float *p_c, *p_gates, *p_scores, *p_vl, *p_nwc, *p_r, *p_loss, *p_acc, *p_wcnt;
    float *p_bc, *p_bcR, *p_Ts, *p_Tr;
    int *p_tok, *p_sl, *p_m;
    __half *h0[2], *h1[2], *W0p, *W1p, *R0p, *R1p, *L0p, *L1p, *S0p, *S1p, *A0p, *A1p;
    __half *T0p, *T1p, *E0p, *E1p, *Fe0p, *Fe1p;
    cudaGetSymbolAddress((void**)&p_c, g_c);
    cudaGetSymbolAddress((void**)&p_gates, g_gates);
    cudaGetSymbolAddress((void**)&p_scores, g_scores);
    cudaGetSymbolAddress((void**)&p_vl, g_vl);
    cudaGetSymbolAddress((void**)&p_nwc, g_nwc);
    cudaGetSymbolAddress((void**)&p_r, g_r);
    cudaGetSymbolAddress((void**)&p_loss, g_loss);
    cudaGetSymbolAddress((void**)&p_acc, g_acc);
    cudaGetSymbolAddress((void**)&p_wcnt, g_wcnt);
    cudaGetSymbolAddress((void**)&p_bc, g_bc);
    cudaGetSymbolAddress((void**)&p_bcR, g_bcR);
    cudaGetSymbolAddress((void**)&p_Ts, g_Ts);
    cudaGetSymbolAddress((void**)&p_Tr, g_Tr);
    cudaGetSymbolAddress((void**)&p_tok, g_tok);
    cudaGetSymbolAddress((void**)&p_sl, g_sl);
    cudaGetSymbolAddress((void**)&p_m, g_m);
    cudaGetSymbolAddress((void**)&h0[0], g_h0a); cudaGetSymbolAddress((void**)&h1[0], g_h1a);
    cudaGetSymbolAddress((void**)&h0[1], g_h0b); cudaGetSymbolAddress((void**)&h1[1], g_h1b);
    cudaGetSymbolAddress((void**)&W0p, g_W0p);  cudaGetSymbolAddress((void**)&W1p, g_W1p);
    cudaGetSymbolAddress((void**)&R0p, g_R0p);  cudaGetSymbolAddress((void**)&R1p, g_R1p);
    cudaGetSymbolAddress((void**)&L0p, g_L0p);  cudaGetSymbolAddress((void**)&L1p, g_L1p);
    cudaGetSymbolAddress((void**)&S0p, g_S0p);  cudaGetSymbolAddress((void**)&S1p, g_S1p);
    cudaGetSymbolAddress((void**)&A0p, g_A0p);  cudaGetSymbolAddress((void**)&A1p, g_A1p);
    cudaGetSymbolAddress((void**)&T0p, g_T0p);  cudaGetSymbolAddress((void**)&T1p, g_T1p);
    cudaGetSymbolAddress((void**)&E0p, g_E0p);  cudaGetSymbolAddress((void**)&E1p, g_E1p);
    cudaGetSymbolAddress((void**)&Fe0p, g_F0p); cudaGetSymbolAddress((void**)&Fe1p, g_F1p);

    const int BH = B * H;

    // ---- setup ----
    build_nwc<<<1, 1024>>>(wcin, p_nwc);
    bias_int<<<(G4H + 255) / 256, 256>>>(bih, bhh, p_bc);
    bias_int<<<(G4H + 255) / 256, 256>>>(rbih, rbhh, p_bcR);
    build_wc_int<<<(G4H * KC + 255) / 256, 256>>>(Wih, Whh, W0p, W1p);
    build_wc_int<<<(G4H * KC + 255) / 256, 256>>>(rWih, rWhh, R0p, R1p);
    split2_kernel<<<(V * H + 255) / 256, 256>>>(lpW, V * H, L0p, L1p);
    split2_kernel<<<(H * F + 255) / 256, 256>>>(affsW, H * F, S0p, S1p);
    split2_kernel<<<(F * H + 255) / 256, 256>>>(affrW, F * H, A0p, A1p);
    split2_kernel<<<(B * F + 255) / 256, 256>>>(target, B * F, T0p, T1p);
    split2_kernel<<<(V * E + 255) / 256, 256>>>(emb_s, V * E, E0p, E1p);
    split2_kernel<<<(V * E + 255) / 256, 256>>>(emb_r, V * E, Fe0p, Fe1p);
    zero_f<<<(BH + 255) / 256, 256>>>(p_c, BH);
    init_sender<<<(B + 255) / 256, 256>>>(p_tok, p_sl, p_vl, p_m);

    // ---- token tables (fp32-accurate; cheap) ----
    hmma3<3><<<dim3(G4H / 128, V / 128), 256, DSM_BYTES>>>(
        E0p, E1p, E, W0p, W1p, KC, p_Ts, G4H, p_bc, E,
        0, nullptr, 0, nullptr, nullptr, nullptr, nullptr);
    hmma3<3><<<dim3(G4H / 128, V / 128), 256, DSM_BYTES>>>(
        Fe0p, Fe1p, E, R0p, R1p, KC, p_Tr, G4H, p_bcR, E,
        0, nullptr, 0, nullptr, nullptr, nullptr, nullptr);

    // ---- h0 = target @ aff_s_W^T + aff_s_b (token-critical: fp32-equivalent) ----
    hmma3<3><<<dim3(H / 128, B / 128), 256, DSM_BYTES>>>(
        T0p, T1p, F, S0p, S1p, F, p_gates, H, affsb, F,
        0, nullptr, 0, nullptr, nullptr, nullptr, nullptr);
    h_split2<<<(BH + 255) / 256, 256>>>(p_gates, h0[0], h1[0]);

    // ---- sender loop (token-critical: fp32-equivalent split-2) ----
    int cur = 0;
    for (int i = 0; i < L; i++) {
        hmma3<3><<<dim3(G4H / 128, B / 128), 256, DSM_BYTES>>>(
            h0[cur], h1[cur], H, W0p + E, W1p + E, KC, nullptr, 0, nullptr, H,
            1, p_tok, 1, p_Ts, p_c, h0[cur ^ 1], h1[cur ^ 1]);
        cur ^= 1;
        hmma3<3><<<dim3(V / 128, B / 128), 256, DSM_BYTES>>>(
            h0[cur], h1[cur], H, L0p, L1p, H, p_scores, V, lpb, H,
            0, nullptr, 0, nullptr, nullptr, nullptr, nullptr);
        score_step<<<B, 256>>>(p_scores, p_nwc, p_tok, p_sl, p_vl, p_m, i);
    }

    pad_m<<<(B * LP1 + 255) / 256, 256>>>(p_m, p_sl);
    zero_f<<<(V + 255) / 256, 256>>>(p_wcnt, V);
    hist_m<<<(B * LP1 + 255) / 256, 256>>>(p_m, p_wcnt);

    // ---- receiver (loss-only: single-pass fp16, 1/3 the MMAs) ----
    zero_f<<<(BH + 255) / 256, 256>>>(p_c, BH);
    zero_h2<<<(BH + 255) / 256, 256>>>(h0[cur], h1[cur], BH);
    for (int t = 0; t < LP1; t++) {
        hmma3<1><<<dim3(G4H / 128, B / 128), 256, DSM_BYTES>>>(
            h0[cur], h1[cur], H, R0p + E, R1p + E, KC, nullptr, 0, nullptr, H,
            1, p_m + t, LP1, p_Tr, p_c, h0[cur ^ 1], h1[cur ^ 1]);
        cur ^= 1;
    }

    // ---- r = hr @ aff_r_W^T + aff_r_b (loss-only: single-pass fp16) ----
    hmma3<1><<<dim3(F / 128, B / 128), 256, DSM_BYTES>>>(
        h0[cur], h1[cur], H, A0p, A1p, H, p_r, F, affrb, H,
        0, nullptr, 0, nullptr, nullptr, nullptr, nullptr);

    hinge_kernel<<<B, 256>>>(target, dis, p_r, p_vl, p_loss, p_acc);
    finalize<<<1, 1024>>>(p_loss, p_acc, out);
    write_m<<<(B * LP1 + 255) / 256, 256>>>(p_m, out);
    write_wc<<<(V + 255) / 256, 256>>>(p_wcnt, out);
}

// round 14
// speedup vs baseline: 1.4050x; 1.0003x over previous
#include <cuda_runtime.h>
#include <cuda_fp16.h>
#include <math.h>
#include <stdint.h>

// Problem dims
#define B     4096
#define F     4096
#define V     1024
#define E     512
#define H     1024
#define L     30
#define G4H   4096
#define KC    1536
#define BOUND 1023
#define LP1   31

// ================= PTX helpers =================
#define CP_ASYNC16(dst, src) asm volatile("cp.async.cg.shared.global [%0], [%1], 16;" :: "r"(dst), "l"(src))
#define CP_COMMIT()          asm volatile("cp.async.commit_group;" ::: "memory")
#define CP_WAIT0()           asm volatile("cp.async.wait_group 0;" ::: "memory")
#define LDMX4(r0,r1,r2,r3, addr) \
    asm volatile("ldmatrix.sync.aligned.m8n8.x4.shared.b16 {%0,%1,%2,%3}, [%4];" \
        : "=r"(r0), "=r"(r1), "=r"(r2), "=r"(r3) : "r"(addr))

__device__ __forceinline__ void mma16816(float* d, const uint32_t* a, uint32_t b0, uint32_t b1)
{
    asm volatile(
        "mma.sync.aligned.m16n8k16.row.col.f32.f16.f16.f32 "
        "{%0,%1,%2,%3}, {%4,%5,%6,%7}, {%8,%9}, {%0,%1,%2,%3};"
        : "+f"(d[0]), "+f"(d[1]), "+f"(d[2]), "+f"(d[3])
        : "r"(a[0]), "r"(a[1]), "r"(a[2]), "r"(a[3]), "r"(b0), "r"(b1));
}

// ================= device scratch =================
__device__ float g_c[B * H];
__device__ float g_gates[B * G4H];
__device__ float g_scores[B * V];
__device__ int   g_tok[B];
__device__ int   g_sl[B];
__device__ float g_vl[B];
__device__ int   g_m[B * LP1];
__device__ float g_nwc[V];
__device__ float g_r[B * F];
__device__ float g_loss[B];
__device__ float g_acc[B];
__device__ float g_wcnt[V];
__device__ float g_bc[G4H];        // interleaved combined bias (sender)
__device__ float g_bcR[G4H];       // interleaved combined bias (receiver)
__device__ float g_Ts[V * G4H];    // emb_s @ Wc^T + bias (interleaved cols)
__device__ float g_Tr[V * G4H];    // emb_r @ Rc^T + bias

// fp16 split-2 planes (plane1 pre-scaled by 2048)
__device__ __half g_h0a[B * H], g_h1a[B * H];
__device__ __half g_h0b[B * H], g_h1b[B * H];
__device__ __half g_W0p[G4H * KC], g_W1p[G4H * KC];
__device__ __half g_R0p[G4H * KC], g_R1p[G4H * KC];
__device__ __half g_L0p[V * H],  g_L1p[V * H];
__device__ __half g_S0p[H * F],  g_S1p[H * F];
__device__ __half g_A0p[F * H],  g_A1p[F * H];
__device__ __half g_T0p[B * F],  g_T1p[B * F];
__device__ __half g_E0p[V * E],  g_E1p[V * E];
__device__ __half g_F0p[V * E],  g_F1p[V * E];

// ================= merged HMMA GEMM =================
// NP=3: split-2 fp16 with compensated cross terms (token-critical, fp32-equivalent).
// NP=1: single-pass plain fp16 (receiver/loss-only path); 2 CTAs/SM.
// mode 0: plain C+bias epilogue.  mode 1: fused LSTM epilogue (Ts gather, c/h update).
#define SMPAD       40
#define TILE_BYTES  (128 * SMPAD * 2)     // 10240
#define STAGE_BYTES (4 * TILE_BYTES)      // 40960
#define DSM_BYTES   (2 * STAGE_BYTES)     // 81920 (NP=3)
#define DSM_NP1     71680                 // NP=1: A0@+0,B0@+2T per stage; stage1 ends 71680; epi 69632+512
#define CS_STRIDE   136

template <int NP>
__device__ __forceinline__ void ld_stage(uint32_t sbase, int buf,
    const __half* __restrict__ A0, const __half* __restrict__ A1, int lda, int m0,
    const __half* __restrict__ B0p, const __half* __restrict__ B1p, int ldb, int n0,
    int k0, int tid)
{
    uint32_t dst0 = sbase + buf * STAGE_BYTES;
#pragma unroll
    for (int t = 0; t < 4; t++) {
        if (NP == 1 && (t == 1 || t == 3)) continue;   // single-pass: only A0, B0
        const __half* pt = (t == 0) ? A0 : (t == 1) ? A1 : (t == 2) ? B0p : B1p;
        const int ld = (t < 2) ? lda : ldb;
        const int r0g = (t < 2) ? m0 : n0;
#pragma unroll
        for (int i = 0; i < 2; i++) {
            int id = tid + i * 256;
            int r = id >> 2, c = id & 3;
            const __half* src = pt + (size_t)(r0g + r) * ld + k0 + c * 8;
            CP_ASYNC16(dst0 + (uint32_t)(t * TILE_BYTES + (r * SMPAD + c * 8) * 2), src);
        }
    }
}

__device__ __forceinline__ void split2h(float x, __half& o0, __half& o1)
{
    __half h0 = __float2half_rn(x);
    float r = (x - __half2float(h0)) * 2048.f;
    o0 = h0;
    o1 = __float2half_rn(r);
}

template <int NP>
__global__ void __launch_bounds__(256, (NP == 1) ? 2 : 1)
hmma3(const __half* __restrict__ A0, const __half* __restrict__ A1, int lda,
      const __half* __restrict__ B0p, const __half* __restrict__ B1p, int ldb,
      float* __restrict__ C, int ldc, const float* __restrict__ bias, int K,
      int mode,
      const int* __restrict__ toks, int tok_stride,
      const float* __restrict__ Ts,
      float* __restrict__ cst, __half* __restrict__ ho0, __half* __restrict__ ho1)
{
    extern __shared__ __align__(16) char dsm[];
    __shared__ int stok[128];

    const int tid = threadIdx.x;
    const int m0 = blockIdx.y * 128, n0 = blockIdx.x * 128;
    if (mode == 1 && tid < 128) stok[tid] = toks[(size_t)(m0 + tid) * tok_stride];

    const int wid = tid >> 5, lane = tid & 31;
    const int wm = wid & 3, wn = wid >> 2;
    const uint32_t sbase = (uint32_t)__cvta_generic_to_shared(dsm);

    float accM[2][8][4], accC[2][8][4];
#pragma unroll
    for (int mt = 0; mt < 2; mt++)
#pragma unroll
        for (int nt = 0; nt < 8; nt++)
#pragma unroll
            for (int q = 0; q < 4; q++) { accM[mt][nt][q] = 0.f; accC[mt][nt][q] = 0.f; }

    const int KT = K >> 5;

    ld_stage<NP>(sbase, 0, A0, A1, lda, m0, B0p, B1p, ldb, n0, 0, tid);
    CP_COMMIT();

    for (int kt = 0; kt < KT; kt++) {
        const int cur = kt & 1;
        CP_WAIT0();
        __syncthreads();
        if (kt + 1 < KT) {
            ld_stage<NP>(sbase, cur ^ 1, A0, A1, lda, m0, B0p, B1p, ldb, n0, (kt + 1) << 5, tid);
            CP_COMMIT();
        }
        const uint32_t bA0 = sbase + cur * STAGE_BYTES;
        const uint32_t bA1 = bA0 + TILE_BYTES;
        const uint32_t bB0 = bA0 + 2 * TILE_BYTES;
        const uint32_t bB1 = bA0 + 3 * TILE_BYTES;
#pragma unroll
        for (int kh = 0; kh < 2; kh++) {
            const int colh = kh * 16 + ((lane >> 4) & 1) * 8;
            uint32_t a0f[2][4], a1f[2][4];
#pragma unroll
            for (int mt = 0; mt < 2; mt++) {
                int row = wm * 32 + mt * 16 + (lane & 15);
                uint32_t off = (uint32_t)((row * SMPAD + colh) * 2);
                LDMX4(a0f[mt][0], a0f[mt][1], a0f[mt][2], a0f[mt][3], bA0 + off);
                if (NP == 3)
                    LDMX4(a1f[mt][0], a1f[mt][1], a1f[mt][2], a1f[mt][3], bA1 + off);
            }
#pragma unroll
            for (int bt = 0; bt < 4; bt++) {
                int row = wn * 64 + bt * 16 + (lane & 15);
                uint32_t off = (uint32_t)((row * SMPAD + colh) * 2);
                uint32_t b0f[4], b1f[4];
                LDMX4(b0f[0], b0f[1], b0f[2], b0f[3], bB0 + off);
                if (NP == 3)
                    LDMX4(b1f[0], b1f[1], b1f[2], b1f[3], bB1 + off);
#pragma unroll
                for (int mt = 0; mt < 2; mt++)
#pragma unroll
                    for (int hi = 0; hi < 2; hi++) {
                        int nt = bt * 2 + hi;
                        mma16816(accM[mt][nt], a0f[mt], b0f[hi], b0f[2 + hi]);
                        if (NP == 3) {
                            mma16816(accC[mt][nt], a0f[mt], b1f[hi], b1f[2 + hi]);
                            mma16816(accC[mt][nt], a1f[mt], b0f[hi], b0f[2 + hi]);
                        }
                    }
            }
        }
    }

    const float cs = 1.f / 2048.f;
    const int g = lane >> 2, q2 = (lane & 3) * 2;

    if (mode == 0) {
#pragma unroll
        for (int mt = 0; mt < 2; mt++) {
            int row = m0 + wm * 32 + mt * 16 + g;
#pragma unroll
            for (int nt = 0; nt < 8; nt++) {
                int col = n0 + wn * 64 + nt * 8 + q2;
                float2 bb = *(const float2*)(bias + col);
                float2 o0 = { accM[mt][nt][0] + accC[mt][nt][0] * cs + bb.x,
                              accM[mt][nt][1] + accC[mt][nt][1] * cs + bb.y };
                float2 o1 = { accM[mt][nt][2] + accC[mt][nt][2] * cs + bb.x,
                              accM[mt][nt][3] + accC[mt][nt][3] * cs + bb.y };
                *(float2*)(C + (size_t)row * ldc + col) = o0;
                *(float2*)(C + (size_t)(row + 8) * ldc + col) = o1;
            }
        }
    } else {
        __syncthreads();
        float* Cs = (float*)dsm;
#pragma unroll
        for (int mt = 0; mt < 2; mt++) {
            int row = wm * 32 + mt * 16 + g;
#pragma unroll
            for (int nt = 0; nt < 8; nt++) {
                int col = wn * 64 + nt * 8 + q2;
                Cs[row * CS_STRIDE + col]           = accM[mt][nt][0] + accC[mt][nt][0] * cs;
                Cs[row * CS_STRIDE + col + 1]       = accM[mt][nt][1] + accC[mt][nt][1] * cs;
                Cs[(row + 8) * CS_STRIDE + col]     = accM[mt][nt][2] + accC[mt][nt][2] * cs;
                Cs[(row + 8) * CS_STRIDE + col + 1] = accM[mt][nt][3] + accC[mt][nt][3] * cs;
            }
        }
        __syncthreads();
        const int ubase = n0 >> 2;
#pragma unroll
        for (int i = 0; i < 16; i++) {
            int idx = tid + i * 256;
            int b = idx >> 5, u = idx & 31;
            int tok = stok[b];
            float4 g4 = *(float4*)&Cs[b * CS_STRIDE + 4 * u];
            float4 t4 = *(const float4*)(Ts + (size_t)tok * G4H + n0 + 4 * u);
            float gi = g4.x + t4.x, gf = g4.y + t4.y, gg = g4.z + t4.z, go = g4.w + t4.w;
            int bg = m0 + b, j = ubase + u;
            size_t ci = (size_t)bg * H + j;
            float cc = cst[ci];
            float si = 1.f / (1.f + expf(-gi));
            float sf = 1.f / (1.f + expf(-gf));
            float so = 1.f / (1.f + expf(-go));
            float nc = sf * cc + si * tanhf(gg);
            cst[ci] = nc;
            float h = so * tanhf(nc);
            split2h(h, ho0[ci], ho1[ci]);
        }
    }
}

// ================= setup / elementwise kernels =================
__global__ void split2_kernel(const float* __restrict__ src, int n,
                              __half* __restrict__ p0, __half* __restrict__ p1)
{
    int i = blockIdx.x * blockDim.x + threadIdx.x;
    if (i < n) split2h(src[i], p0[i], p1[i]);
}

__global__ void build_wc_int(const float* __restrict__ Wih, const float* __restrict__ Whh,
                             __half* __restrict__ p0, __half* __restrict__ p1)
{
    int idx = blockIdx.x * blockDim.x + threadIdx.x;
    if (idx >= G4H * KC) return;
    int n = idx / KC, k = idx % KC;
    int u = n >> 2, gg = n & 3;
    int orig = gg * H + u;
    float w = (k < E) ? Wih[orig * E + k] : Whh[orig * H + (k - E)];
    split2h(w, p0[idx], p1[idx]);
}

__global__ void bias_int(const float* __restrict__ bih, const float* __restrict__ bhh,
                         float* __restrict__ bc)
{
    int n = blockIdx.x * blockDim.x + threadIdx.x;
    if (n >= G4H) return;
    int u = n >> 2, gg = n & 3;
    int orig = gg * H + u;
    bc[n] = bih[orig] + bhh[orig];
}

__global__ void zero_f(float* p, int n)
{
    int i = blockIdx.x * blockDim.x + threadIdx.x;
    if (i < n) p[i] = 0.f;
}

__global__ void zero_h2(__half* p0, __half* p1, int n)
{
    int i = blockIdx.x * blockDim.x + threadIdx.x;
    if (i < n) { p0[i] = __float2half(0.f); p1[i] = __float2half(0.f); }
}

__global__ void build_nwc(const float* __restrict__ wc, float* __restrict__ nwc)
{
    __shared__ float red[1024];
    int t = threadIdx.x;
    float w = wc[t] * (t == BOUND ? 0.1f : 1.0f);
    red[t] = w;
    __syncthreads();
    for (int off = 512; off; off >>= 1) {
        if (t < off) red[t] += red[t + off];
        __syncthreads();
    }
    float denom = red[0];
    nwc[t] = (denom > 0.f) ? (w / denom) : w;
}

__global__ void init_sender(int* tok, int* sl, float* vl, int* m)
{
    int b = blockIdx.x * blockDim.x + threadIdx.x;
    if (b < B) {
        tok[b] = BOUND;
        sl[b] = LP1;
        vl[b] = 0.f;
        m[b * LP1] = BOUND;
    }
}

__global__ void h_split2(const float* __restrict__ hsrc,
                         __half* __restrict__ h0p, __half* __restrict__ h1p)
{
    int idx = blockIdx.x * blockDim.x + threadIdx.x;
    if (idx >= B * H) return;
    split2h(hsrc[idx], h0p[idx], h1p[idx]);
}

__global__ void score_step(const float* __restrict__ scores, const float* __restrict__ nwc,
                           int* tok, int* sl, float* vl, int* m, int step)
{
    __shared__ float sBest[256];
    __shared__ int   sIdx[256];
    __shared__ float sLM[256];
    __shared__ float sSum[256];
    int b = blockIdx.x, tid = threadIdx.x;
    const float* srow = scores + (size_t)b * V;

    float best = -1e30f; int bidx = 0; float lmax = -1e30f;
    for (int v = tid; v < V; v += 256) {
        float s = srow[v];
        if (s > best) { best = s; bidx = v; }
        float lg = s - nwc[v];
        lmax = fmaxf(lmax, lg);
    }
    sBest[tid] = best; sIdx[tid] = bidx; sLM[tid] = lmax;
    __syncthreads();
    for (int off = 128; off; off >>= 1) {
        if (tid < off) {
            float ob = sBest[tid + off]; int oi = sIdx[tid + off];
            if (ob > sBest[tid] || (ob == sBest[tid] && oi < sIdx[tid])) { sBest[tid] = ob; sIdx[tid] = oi; }
            sLM[tid] = fmaxf(sLM[tid], sLM[tid + off]);
        }
        __syncthreads();
    }
    float LM = sLM[0];
    int t = sIdx[0];
    __syncthreads();

    float ssum = 0.f;
    for (int v = tid; v < V; v += 256) ssum += __expf(srow[v] - nwc[v] - LM);
    sSum[tid] = ssum;
    __syncthreads();
    for (int off = 128; off; off >>= 1) {
        if (tid < off) sSum[tid] += sSum[tid + off];
        __syncthreads();
    }
    if (tid == 0) {
        float ce = __logf(sSum[0]) + LM - (srow[t] - nwc[t]);
        vl[b] += ce;
        tok[b] = t;
        if (t == BOUND && sl[b] == LP1) sl[b] = step + 2;
        m[b * LP1 + step + 1] = t;
    }
}

__global__ void pad_m(int* __restrict__ m, const int* __restrict__ sl)
{
    int idx = blockIdx.x * blockDim.x + threadIdx.x;
    if (idx >= B * LP1) return;
    int b = idx / LP1, pos = idx % LP1;
    if (pos >= sl[b]) m[idx] = BOUND;
}

__global__ void hist_m(const int* __restrict__ m, float* __restrict__ wcnt)
{
    int idx = blockIdx.x * blockDim.x + threadIdx.x;
    if (idx < B * LP1) atomicAdd(&wcnt[m[idx]], 1.0f);
}

__global__ void hinge_kernel(const float* __restrict__ target, const float* __restrict__ dis,
                             const float* __restrict__ r, const float* __restrict__ vl,
                             float* __restrict__ loss, float* __restrict__ acc)
{
    __shared__ float red[4][257];
    int b = blockIdx.x, t = threadIdx.x;
    const float* rr = r + (size_t)b * F;
    const float* tg = target + (size_t)b * F;
    float s0 = 0.f, s1 = 0.f, s2 = 0.f, s3 = 0.f;
    for (int f = t; f < F; f += 256) {
        float rv = rr[f];
        s0 += tg[f] * rv;
        s1 += dis[(size_t)0 * B * F + (size_t)b * F + f] * rv;
        s2 += dis[(size_t)1 * B * F + (size_t)b * F + f] * rv;
        s3 += dis[(size_t)2 * B * F + (size_t)b * F + f] * rv;
    }
    red[0][t] = s0; red[1][t] = s1; red[2][t] = s2; red[3][t] = s3;
    __syncthreads();
    for (int off = 128; off; off >>= 1) {
        if (t < off) {
#pragma unroll
            for (int q = 0; q < 4; q++) red[q][t] += red[q][t + off];
        }
        __syncthreads();
    }
    if (t == 0) {
        float ts = red[0][0], d0 = red[1][0], d1 = red[2][0], d2 = red[3][0];
        float lo = fmaxf(0.f, 1.f - ts + d0) + fmaxf(0.f, 1.f - ts + d1) + fmaxf(0.f, 1.f - ts + d2);
        loss[b] = lo + 0.1f * vl[b];
        acc[b] = (ts >= d0 && ts >= d1 && ts >= d2) ? 1.f : 0.f;
    }
}

__global__ void finalize(const float* __restrict__ loss, const float* __restrict__ acc, float* __restrict__ out)
{
    __shared__ float rl[1024], ra[1024];
    int t = threadIdx.x;
    float s = 0.f, a = 0.f;
    for (int i = t; i < B; i += 1024) { s += loss[i]; a += acc[i]; }
    rl[t] = s; ra[t] = a;
    __syncthreads();
    for (int off = 512; off; off >>= 1) {
        if (t < off) { rl[t] += rl[t + off]; ra[t] += ra[t + off]; }
        __syncthreads();
    }
    if (t == 0) { out[0] = rl[0] / (float)B; out[1] = ra[0] / (float)B; }
}

__global__ void write_m(const int* __restrict__ m, float* __restrict__ out)
{
    int idx = blockIdx.x * blockDim.x + threadIdx.x;
    if (idx < B * LP1) out[2 + idx] = (float)m[idx];
}

__global__ void write_wc(const float* __restrict__ wcnt, float* __restrict__ out)
{
    int v = blockIdx.x * blockDim.x + threadIdx.x;
    if (v < V) out[2 + B * LP1 + v] = wcnt[v];
}

// ================= launch =================
extern "C" void kernel_launch(void* const* d_in, const int* in_sizes, int n_in,
                              void* d_out, int out_size)
{
    const float* target = (const float*)d_in[0];
    const float* dis    = (const float*)d_in[1];
    const float* wcin   = (const float*)d_in[2];
    const float* emb_s  = (const float*)d_in[3];
    const float* affsW  = (const float*)d_in[4];
    const float* affsb  = (const float*)d_in[5];
    const float* Wih    = (const float*)d_in[6];
    const float* Whh    = (const float*)d_in[7];
    const float* bih    = (const float*)d_in[8];
    const float* bhh    = (const float*)d_in[9];
    const float* lpW    = (const float*)d_in[10];
    const float* lpb    = (const float*)d_in[11];
    const float* emb_r  = (const float*)d_in[12];
    const float* rWih   = (const float*)d_in[13];
    const float* rWhh   = (const float*)d_in[14];
    const float* rbih   = (const float*)d_in[15];
    const float* rbhh   = (const float*)d_in[16];
    const float* affrW  = (const float*)d_in[17];
    const float* affrb  = (const float*)d_in[18];
    float* out = (float*)d_out;

    cudaFuncSetAttribute(hmma3<3>, cudaFuncAttributeMaxDynamicSharedMemorySize, DSM_BYTES);
    cudaFuncSetAttribute(hmma3<1>, cudaFuncAttributeMaxDynamicSharedMemorySize, DSM_NP1);

    float *p_c, *p_gates, *p_scores, *p_vl, *p_nwc, *p_r, *p_loss, *p_acc, *p_wcnt;
    float *p_bc, *p_bcR, *p_Ts, *p_Tr;
    int *p_tok, *p_sl, *p_m;
    __half *h0[2], *h1[2], *W0p, *W1p, *R0p, *R1p, *L0p, *L1p, *S0p, *S1p, *A0p, *A1p;
    __half *T0p, *T1p, *E0p, *E1p, *Fe0p, *Fe1p;
    cudaGetSymbolAddress((void**)&p_c, g_c);
    cudaGetSymbolAddress((void**)&p_gates, g_gates);
    cudaGetSymbolAddress((void**)&p_scores, g_scores);
    cudaGetSymbolAddress((void**)&p_vl, g_vl);
    cudaGetSymbolAddress((void**)&p_nwc, g_nwc);
    cudaGetSymbolAddress((void**)&p_r, g_r);
    cudaGetSymbolAddress((void**)&p_loss, g_loss);
    cudaGetSymbolAddress((void**)&p_acc, g_acc);
    cudaGetSymbolAddress((void**)&p_wcnt, g_wcnt);
    cudaGetSymbolAddress((void**)&p_bc, g_bc);
    cudaGetSymbolAddress((void**)&p_bcR, g_bcR);
    cudaGetSymbolAddress((void**)&p_Ts, g_Ts);
    cudaGetSymbolAddress((void**)&p_Tr, g_Tr);
    cudaGetSymbolAddress((void**)&p_tok, g_tok);
    cudaGetSymbolAddress((void**)&p_sl, g_sl);
    cudaGetSymbolAddress((void**)&p_m, g_m);
    cudaGetSymbolAddress((void**)&h0[0], g_h0a); cudaGetSymbolAddress((void**)&h1[0], g_h1a);
    cudaGetSymbolAddress((void**)&h0[1], g_h0b); cudaGetSymbolAddress((void**)&h1[1], g_h1b);
    cudaGetSymbolAddress((void**)&W0p, g_W0p);  cudaGetSymbolAddress((void**)&W1p, g_W1p);
    cudaGetSymbolAddress((void**)&R0p, g_R0p);  cudaGetSymbolAddress((void**)&R1p, g_R1p);
    cudaGetSymbolAddress((void**)&L0p, g_L0p);  cudaGetSymbolAddress((void**)&L1p, g_L1p);
    cudaGetSymbolAddress((void**)&S0p, g_S0p);  cudaGetSymbolAddress((void**)&S1p, g_S1p);
    cudaGetSymbolAddress((void**)&A0p, g_A0p);  cudaGetSymbolAddress((void**)&A1p, g_A1p);
    cudaGetSymbolAddress((void**)&T0p, g_T0p);  cudaGetSymbolAddress((void**)&T1p, g_T1p);
    cudaGetSymbolAddress((void**)&E0p, g_E0p);  cudaGetSymbolAddress((void**)&E1p, g_E1p);
    cudaGetSymbolAddress((void**)&Fe0p, g_F0p); cudaGetSymbolAddress((void**)&Fe1p, g_F1p);

    const int BH = B * H;

    // ---- setup ----
    build_nwc<<<1, 1024>>>(wcin, p_nwc);
    bias_int<<<(G4H + 255) / 256, 256>>>(bih, bhh, p_bc);
    bias_int<<<(G4H + 255) / 256, 256>>>(rbih, rbhh, p_bcR);
    build_wc_int<<<(G4H * KC + 255) / 256, 256>>>(Wih, Whh, W0p, W1p);
    build_wc_int<<<(G4H * KC + 255) / 256, 256>>>(rWih, rWhh, R0p, R1p);
    split2_kernel<<<(V * H + 255) / 256, 256>>>(lpW, V * H, L0p, L1p);
    split2_kernel<<<(H * F + 255) / 256, 256>>>(affsW, H * F, S0p, S1p);
    split2_kernel<<<(F * H + 255) / 256, 256>>>(affrW, F * H, A0p, A1p);
    split2_kernel<<<(B * F + 255) / 256, 256>>>(target, B * F, T0p, T1p);
    split2_kernel<<<(V * E + 255) / 256, 256>>>(emb_s, V * E, E0p, E1p);
    split2_kernel<<<(V * E + 255) / 256, 256>>>(emb_r, V * E, Fe0p, Fe1p);
    zero_f<<<(BH + 255) / 256, 256>>>(p_c, BH);
    init_sender<<<(B + 255) / 256, 256>>>(p_tok, p_sl, p_vl, p_m);

    // ---- token tables (fp32-accurate; cheap) ----
    hmma3<3><<<dim3(G4H / 128, V / 128), 256, DSM_BYTES>>>(
        E0p, E1p, E, W0p, W1p, KC, p_Ts, G4H, p_bc, E,
        0, nullptr, 0, nullptr, nullptr, nullptr, nullptr);
    hmma3<3><<<dim3(G4H / 128, V / 128), 256, DSM_BYTES>>>(
        Fe0p, Fe1p, E, R0p, R1p, KC, p_Tr, G4H, p_bcR, E,
        0, nullptr, 0, nullptr, nullptr, nullptr, nullptr);

    // ---- h0 = target @ aff_s_W^T + aff_s_b (token-critical: fp32-equivalent) ----
    hmma3<3><<<dim3(H / 128, B / 128), 256, DSM_BYTES>>>(
        T0p, T1p, F, S0p, S1p, F, p_gates, H, affsb, F,
        0, nullptr, 0, nullptr, nullptr, nullptr, nullptr);
    h_split2<<<(BH + 255) / 256, 256>>>(p_gates, h0[0], h1[0]);

    // ---- sender loop (token-critical: fp32-equivalent split-2) ----
    int cur = 0;
    for (int i = 0; i < L; i++) {
        hmma3<3><<<dim3(G4H / 128, B / 128), 256, DSM_BYTES>>>(
            h0[cur], h1[cur], H, W0p + E, W1p + E, KC, nullptr, 0, nullptr, H,
            1, p_tok, 1, p_Ts, p_c, h0[cur ^ 1], h1[cur ^ 1]);
        cur ^= 1;
        hmma3<3><<<dim3(V / 128, B / 128), 256, DSM_BYTES>>>(
            h0[cur], h1[cur], H, L0p, L1p, H, p_scores, V, lpb, H,
            0, nullptr, 0, nullptr, nullptr, nullptr, nullptr);
        score_step<<<B, 256>>>(p_scores, p_nwc, p_tok, p_sl, p_vl, p_m, i);
    }

    pad_m<<<(B * LP1 + 255) / 256, 256>>>(p_m, p_sl);
    zero_f<<<(V + 255) / 256, 256>>>(p_wcnt, V);
    hist_m<<<(B * LP1 + 255) / 256, 256>>>(p_m, p_wcnt);

    // ---- receiver (loss-only: single-pass fp16, 2 CTAs/SM) ----
    zero_f<<<(BH + 255) / 256, 256>>>(p_c, BH);
    zero_h2<<<(BH + 255) / 256, 256>>>(h0[cur], h1[cur], BH);
    for (int t = 0; t < LP1; t++) {
        hmma3<1><<<dim3(G4H / 128, B / 128), 256, DSM_NP1>>>(
            h0[cur], h1[cur], H, R0p + E, R1p + E, KC, nullptr, 0, nullptr, H,
            1, p_m + t, LP1, p_Tr, p_c, h0[cur ^ 1], h1[cur ^ 1]);
        cur ^= 1;
    }

    // ---- r = hr @ aff_r_W^T + aff_r_b (loss-only: single-pass fp16) ----
    hmma3<1><<<dim3(F / 128, B / 128), 256, DSM_NP1>>>(
        h0[cur], h1[cur], H, A0p, A1p, H, p_r, F, affrb, H,
        0, nullptr, 0, nullptr, nullptr, nullptr, nullptr);

    hinge_kernel<<<B, 256>>>(target, dis, p_r, p_vl, p_loss, p_acc);
    finalize<<<1, 1024>>>(p_loss, p_acc, out);
    write_m<<<(B * LP1 + 255) / 256, 256>>>(p_m, out);
    write_wc<<<(V + 255) / 256, 256>>>(p_wcnt, out);
}

// round 15
// speedup vs baseline: 1.4381x; 1.0235x over previous
#include <cuda_runtime.h>
#include <cuda_fp16.h>
#include <math.h>
#include <stdint.h>

// Problem dims
#define B     4096
#define F     4096
#define V     1024
#define E     512
#define H     1024
#define L     30
#define G4H   4096
#define KC    1536
#define BOUND 1023
#define LP1   31

// ================= PTX helpers =================
#define CP_ASYNC16(dst, src) asm volatile("cp.async.cg.shared.global [%0], [%1], 16;" :: "r"(dst), "l"(src))
#define CP_COMMIT()          asm volatile("cp.async.commit_group;" ::: "memory")
#define CP_WAIT0()           asm volatile("cp.async.wait_group 0;" ::: "memory")
#define LDMX4(r0,r1,r2,r3, addr) \
    asm volatile("ldmatrix.sync.aligned.m8n8.x4.shared.b16 {%0,%1,%2,%3}, [%4];" \
        : "=r"(r0), "=r"(r1), "=r"(r2), "=r"(r3) : "r"(addr))

__device__ __forceinline__ void mma16816(float* d, const uint32_t* a, uint32_t b0, uint32_t b1)
{
    asm volatile(
        "mma.sync.aligned.m16n8k16.row.col.f32.f16.f16.f32 "
        "{%0,%1,%2,%3}, {%4,%5,%6,%7}, {%8,%9}, {%0,%1,%2,%3};"
        : "+f"(d[0]), "+f"(d[1]), "+f"(d[2]), "+f"(d[3])
        : "r"(a[0]), "r"(a[1]), "r"(a[2]), "r"(a[3]), "r"(b0), "r"(b1));
}

// ================= device scratch =================
__device__ float g_c[B * H];
__device__ float g_gates[B * G4H];
__device__ float g_scores[B * V];
__device__ int   g_tok[B];
__device__ int   g_sl[B];
__device__ float g_vl[B];
__device__ int   g_m[B * LP1];
__device__ float g_nwc[V];
__device__ float g_r[B * F];
__device__ float g_loss[B];
__device__ float g_acc[B];
__device__ float g_wcnt[V];
__device__ float g_bc[G4H];        // interleaved combined bias (sender)
__device__ float g_bcR[G4H];       // interleaved combined bias (receiver)
__device__ float g_Ts[V * G4H];    // emb_s @ Wc^T + bias (interleaved cols)
__device__ float g_Tr[V * G4H];    // emb_r @ Rc^T + bias

// fp16 split-2 planes (plane1 pre-scaled by 2048)
__device__ __half g_h0a[B * H], g_h1a[B * H];
__device__ __half g_h0b[B * H], g_h1b[B * H];
__device__ __half g_W0p[G4H * KC], g_W1p[G4H * KC];
__device__ __half g_R0p[G4H * KC], g_R1p[G4H * KC];
__device__ __half g_L0p[V * H],  g_L1p[V * H];
__device__ __half g_S0p[H * F],  g_S1p[H * F];
__device__ __half g_A0p[F * H],  g_A1p[F * H];
__device__ __half g_T0p[B * F],  g_T1p[B * F];
__device__ __half g_E0p[V * E],  g_E1p[V * E];
__device__ __half g_F0p[V * E],  g_F1p[V * E];

// ================= merged HMMA GEMM =================
// 512 threads, 16 warps (4x4), warp tile 32x32. Identical MMA sequence per
// output element as the 256-thread version -> bitwise identical results.
// NP=3: split-2 fp16 with compensated cross terms (token-critical).
// NP=1: single-pass plain fp16 (receiver/loss-only path).
#define SMPAD       40
#define TILE_BYTES  (128 * SMPAD * 2)     // 10240
#define STAGE_BYTES (4 * TILE_BYTES)      // 40960
#define DSM_BYTES   (2 * STAGE_BYTES)     // 81920 (NP=3)
#define DSM_NP1     71680                 // NP=1 uses A0/B0 slots only
#define CS_STRIDE   136

template <int NP>
__device__ __forceinline__ void ld_stage(uint32_t sbase, int buf,
    const __half* __restrict__ A0, const __half* __restrict__ A1, int lda, int m0,
    const __half* __restrict__ B0p, const __half* __restrict__ B1p, int ldb, int n0,
    int k0, int tid)
{
    uint32_t dst0 = sbase + buf * STAGE_BYTES;
    const int r = tid >> 2, c = tid & 3;      // 512 threads = 512 chunks/tile
#pragma unroll
    for (int t = 0; t < 4; t++) {
        if (NP == 1 && (t == 1 || t == 3)) continue;
        const __half* pt = (t == 0) ? A0 : (t == 1) ? A1 : (t == 2) ? B0p : B1p;
        const int ld = (t < 2) ? lda : ldb;
        const int r0g = (t < 2) ? m0 : n0;
        const __half* src = pt + (size_t)(r0g + r) * ld + k0 + c * 8;
        CP_ASYNC16(dst0 + (uint32_t)(t * TILE_BYTES + (r * SMPAD + c * 8) * 2), src);
    }
}

__device__ __forceinline__ void split2h(float x, __half& o0, __half& o1)
{
    __half h0 = __float2half_rn(x);
    float r = (x - __half2float(h0)) * 2048.f;
    o0 = h0;
    o1 = __float2half_rn(r);
}

template <int NP>
__global__ void __launch_bounds__(512, 1)
hmma3(const __half* __restrict__ A0, const __half* __restrict__ A1, int lda,
      const __half* __restrict__ B0p, const __half* __restrict__ B1p, int ldb,
      float* __restrict__ C, int ldc, const float* __restrict__ bias, int K,
      int mode,
      const int* __restrict__ toks, int tok_stride,
      const float* __restrict__ Ts,
      float* __restrict__ cst, __half* __restrict__ ho0, __half* __restrict__ ho1)
{
    extern __shared__ __align__(16) char dsm[];
    __shared__ int stok[128];

    const int tid = threadIdx.x;
    const int m0 = blockIdx.y * 128, n0 = blockIdx.x * 128;
    if (mode == 1 && tid < 128) stok[tid] = toks[(size_t)(m0 + tid) * tok_stride];

    const int wid = tid >> 5, lane = tid & 31;
    const int wm = wid & 3, wn = wid >> 2;    // 4x4 warp grid, warp tile 32x32
    const uint32_t sbase = (uint32_t)__cvta_generic_to_shared(dsm);

    float accM[2][4][4], accC[2][4][4];
#pragma unroll
    for (int mt = 0; mt < 2; mt++)
#pragma unroll
        for (int nt = 0; nt < 4; nt++)
#pragma unroll
            for (int q = 0; q < 4; q++) { accM[mt][nt][q] = 0.f; accC[mt][nt][q] = 0.f; }

    const int KT = K >> 5;

    ld_stage<NP>(sbase, 0, A0, A1, lda, m0, B0p, B1p, ldb, n0, 0, tid);
    CP_COMMIT();

    for (int kt = 0; kt < KT; kt++) {
        const int cur = kt & 1;
        CP_WAIT0();
        __syncthreads();
        if (kt + 1 < KT) {
            ld_stage<NP>(sbase, cur ^ 1, A0, A1, lda, m0, B0p, B1p, ldb, n0, (kt + 1) << 5, tid);
            CP_COMMIT();
        }
        const uint32_t bA0 = sbase + cur * STAGE_BYTES;
        const uint32_t bA1 = bA0 + TILE_BYTES;
        const uint32_t bB0 = bA0 + 2 * TILE_BYTES;
        const uint32_t bB1 = bA0 + 3 * TILE_BYTES;
#pragma unroll
        for (int kh = 0; kh < 2; kh++) {
            const int colh = kh * 16 + ((lane >> 4) & 1) * 8;
            uint32_t a0f[2][4], a1f[2][4];
#pragma unroll
            for (int mt = 0; mt < 2; mt++) {
                int row = wm * 32 + mt * 16 + (lane & 15);
                uint32_t off = (uint32_t)((row * SMPAD + colh) * 2);
                LDMX4(a0f[mt][0], a0f[mt][1], a0f[mt][2], a0f[mt][3], bA0 + off);
                if (NP == 3)
                    LDMX4(a1f[mt][0], a1f[mt][1], a1f[mt][2], a1f[mt][3], bA1 + off);
            }
#pragma unroll
            for (int bt = 0; bt < 2; bt++) {
                int row = wn * 32 + bt * 16 + (lane & 15);
                uint32_t off = (uint32_t)((row * SMPAD + colh) * 2);
                uint32_t b0f[4], b1f[4];
                LDMX4(b0f[0], b0f[1], b0f[2], b0f[3], bB0 + off);
                if (NP == 3)
                    LDMX4(b1f[0], b1f[1], b1f[2], b1f[3], bB1 + off);
#pragma unroll
                for (int mt = 0; mt < 2; mt++)
#pragma unroll
                    for (int hi = 0; hi < 2; hi++) {
                        int nt = bt * 2 + hi;
                        mma16816(accM[mt][nt], a0f[mt], b0f[hi], b0f[2 + hi]);
                        if (NP == 3) {
                            mma16816(accC[mt][nt], a0f[mt], b1f[hi], b1f[2 + hi]);
                            mma16816(accC[mt][nt], a1f[mt], b0f[hi], b0f[2 + hi]);
                        }
                    }
            }
        }
    }

    const float cs = 1.f / 2048.f;
    const int g = lane >> 2, q2 = (lane & 3) * 2;

    if (mode == 0) {
#pragma unroll
        for (int mt = 0; mt < 2; mt++) {
            int row = m0 + wm * 32 + mt * 16 + g;
#pragma unroll
            for (int nt = 0; nt < 4; nt++) {
                int col = n0 + wn * 32 + nt * 8 + q2;
                float2 bb = *(const float2*)(bias + col);
                float2 o0 = { accM[mt][nt][0] + accC[mt][nt][0] * cs + bb.x,
                              accM[mt][nt][1] + accC[mt][nt][1] * cs + bb.y };
                float2 o1 = { accM[mt][nt][2] + accC[mt][nt][2] * cs + bb.x,
                              accM[mt][nt][3] + accC[mt][nt][3] * cs + bb.y };
                *(float2*)(C + (size_t)row * ldc + col) = o0;
                *(float2*)(C + (size_t)(row + 8) * ldc + col) = o1;
            }
        }
    } else {
        __syncthreads();
        float* Cs = (float*)dsm;
#pragma unroll
        for (int mt = 0; mt < 2; mt++) {
            int row = wm * 32 + mt * 16 + g;
#pragma unroll
            for (int nt = 0; nt < 4; nt++) {
                int col = wn * 32 + nt * 8 + q2;
                Cs[row * CS_STRIDE + col]           = accM[mt][nt][0] + accC[mt][nt][0] * cs;
                Cs[row * CS_STRIDE + col + 1]       = accM[mt][nt][1] + accC[mt][nt][1] * cs;
                Cs[(row + 8) * CS_STRIDE + col]     = accM[mt][nt][2] + accC[mt][nt][2] * cs;
                Cs[(row + 8) * CS_STRIDE + col + 1] = accM[mt][nt][3] + accC[mt][nt][3] * cs;
            }
        }
        __syncthreads();
        const int ubase = n0 >> 2;
#pragma unroll
        for (int i = 0; i < 8; i++) {
            int idx = tid + i * 512;
            int b = idx >> 5, u = idx & 31;
            int tok = stok[b];
            float4 g4 = *(float4*)&Cs[b * CS_STRIDE + 4 * u];
            float4 t4 = *(const float4*)(Ts + (size_t)tok * G4H + n0 + 4 * u);
            float gi = g4.x + t4.x, gf = g4.y + t4.y, gg = g4.z + t4.z, go = g4.w + t4.w;
            int bg = m0 + b, j = ubase + u;
            size_t ci = (size_t)bg * H + j;
            float cc = cst[ci];
            float si = 1.f / (1.f + expf(-gi));
            float sf = 1.f / (1.f + expf(-gf));
            float so = 1.f / (1.f + expf(-go));
            float nc = sf * cc + si * tanhf(gg);
            cst[ci] = nc;
            float h = so * tanhf(nc);
            split2h(h, ho0[ci], ho1[ci]);
        }
    }
}

// ================= setup / elementwise kernels =================
__global__ void split2_kernel(const float* __restrict__ src, int n,
                              __half* __restrict__ p0, __half* __restrict__ p1)
{
    int i = blockIdx.x * blockDim.x + threadIdx.x;
    if (i < n) split2h(src[i], p0[i], p1[i]);
}

__global__ void build_wc_int(const float* __restrict__ Wih, const float* __restrict__ Whh,
                             __half* __restrict__ p0, __half* __restrict__ p1)
{
    int idx = blockIdx.x * blockDim.x + threadIdx.x;
    if (idx >= G4H * KC) return;
    int n = idx / KC, k = idx % KC;
    int u = n >> 2, gg = n & 3;
    int orig = gg * H + u;
    float w = (k < E) ? Wih[orig * E + k] : Whh[orig * H + (k - E)];
    split2h(w, p0[idx], p1[idx]);
}

__global__ void bias_int(const float* __restrict__ bih, const float* __restrict__ bhh,
                         float* __restrict__ bc)
{
    int n = blockIdx.x * blockDim.x + threadIdx.x;
    if (n >= G4H) return;
    int u = n >> 2, gg = n & 3;
    int orig = gg * H + u;
    bc[n] = bih[orig] + bhh[orig];
}

__global__ void zero_f(float* p, int n)
{
    int i = blockIdx.x * blockDim.x + threadIdx.x;
    if (i < n) p[i] = 0.f;
}

__global__ void zero_h2(__half* p0, __half* p1, int n)
{
    int i = blockIdx.x * blockDim.x + threadIdx.x;
    if (i < n) { p0[i] = __float2half(0.f); p1[i] = __float2half(0.f); }
}

__global__ void build_nwc(const float* __restrict__ wc, float* __restrict__ nwc)
{
    __shared__ float red[1024];
    int t = threadIdx.x;
    float w = wc[t] * (t == BOUND ? 0.1f : 1.0f);
    red[t] = w;
    __syncthreads();
    for (int off = 512; off; off >>= 1) {
        if (t < off) red[t] += red[t + off];
        __syncthreads();
    }
    float denom = red[0];
    nwc[t] = (denom > 0.f) ? (w / denom) : w;
}

__global__ void init_sender(int* tok, int* sl, float* vl, int* m)
{
    int b = blockIdx.x * blockDim.x + threadIdx.x;
    if (b < B) {
        tok[b] = BOUND;
        sl[b] = LP1;
        vl[b] = 0.f;
        m[b * LP1] = BOUND;
    }
}

__global__ void h_split2(const float* __restrict__ hsrc,
                         __half* __restrict__ h0p, __half* __restrict__ h1p)
{
    int idx = blockIdx.x * blockDim.x + threadIdx.x;
    if (idx >= B * H) return;
    split2h(hsrc[idx], h0p[idx], h1p[idx]);
}

__global__ void score_step(const float* __restrict__ scores, const float* __restrict__ nwc,
                           int* tok, int* sl, float* vl, int* m, int step)
{
    __shared__ float sBest[256];
    __shared__ int   sIdx[256];
    __shared__ float sLM[256];
    __shared__ float sSum[256];
    int b = blockIdx.x, tid = threadIdx.x;
    const float* srow = scores + (size_t)b * V;

    float best = -1e30f; int bidx = 0; float lmax = -1e30f;
    for (int v = tid; v < V; v += 256) {
        float s = srow[v];
        if (s > best) { best = s; bidx = v; }
        float lg = s - nwc[v];
        lmax = fmaxf(lmax, lg);
    }
    sBest[tid] = best; sIdx[tid] = bidx; sLM[tid] = lmax;
    __syncthreads();
    for (int off = 128; off; off >>= 1) {
        if (tid < off) {
            float ob = sBest[tid + off]; int oi = sIdx[tid + off];
            if (ob > sBest[tid] || (ob == sBest[tid] && oi < sIdx[tid])) { sBest[tid] = ob; sIdx[tid] = oi; }
            sLM[tid] = fmaxf(sLM[tid], sLM[tid + off]);
        }
        __syncthreads();
    }
    float LM = sLM[0];
    int t = sIdx[0];
    __syncthreads();

    float ssum = 0.f;
    for (int v = tid; v < V; v += 256) ssum += __expf(srow[v] - nwc[v] - LM);
    sSum[tid] = ssum;
    __syncthreads();
    for (int off = 128; off; off >>= 1) {
        if (tid < off) sSum[tid] += sSum[tid + off];
        __syncthreads();
    }
    if (tid == 0) {
        float ce = __logf(sSum[0]) + LM - (srow[t] - nwc[t]);
        vl[b] += ce;
        tok[b] = t;
        if (t == BOUND && sl[b] == LP1) sl[b] = step + 2;
        m[b * LP1 + step + 1] = t;
    }
}

__global__ void pad_m(int* __restrict__ m, const int* __restrict__ sl)
{
    int idx = blockIdx.x * blockDim.x + threadIdx.x;
    if (idx >= B * LP1) return;
    int b = idx / LP1, pos = idx % LP1;
    if (pos >= sl[b]) m[idx] = BOUND;
}

__global__ void hist_m(const int* __restrict__ m, float* __restrict__ wcnt)
{
    int idx = blockIdx.x * blockDim.x + threadIdx.x;
    if (idx < B * LP1) atomicAdd(&wcnt[m[idx]], 1.0f);
}

__global__ void hinge_kernel(const float* __restrict__ target, const float* __restrict__ dis,
                             const float* __restrict__ r, const float* __restrict__ vl,
                             float* __restrict__ loss, float* __restrict__ acc)
{
    __shared__ float red[4][257];
    int b = blockIdx.x, t = threadIdx.x;
    const float* rr = r + (size_t)b * F;
    const float* tg = target + (size_t)b * F;
    float s0 = 0.f, s1 = 0.f, s2 = 0.f, s3 = 0.f;
    for (int f = t; f < F; f += 256) {
        float rv = rr[f];
        s0 += tg[f] * rv;
        s1 += dis[(size_t)0 * B * F + (size_t)b * F + f] * rv;
        s2 += dis[(size_t)1 * B * F + (size_t)b * F + f] * rv;
        s3 += dis[(size_t)2 * B * F + (size_t)b * F + f] * rv;
    }
    red[0][t] = s0; red[1][t] = s1; red[2][t] = s2; red[3][t] = s3;
    __syncthreads();
    for (int off = 128; off; off >>= 1) {
        if (t < off) {
#pragma unroll
            for (int q = 0; q < 4; q++) red[q][t] += red[q][t + off];
        }
        __syncthreads();
    }
    if (t == 0) {
        float ts = red[0][0], d0 = red[1][0], d1 = red[2][0], d2 = red[3][0];
        float lo = fmaxf(0.f, 1.f - ts + d0) + fmaxf(0.f, 1.f - ts + d1) + fmaxf(0.f, 1.f - ts + d2);
        loss[b] = lo + 0.1f * vl[b];
        acc[b] = (ts >= d0 && ts >= d1 && ts >= d2) ? 1.f : 0.f;
    }
}

__global__ void finalize(const float* __restrict__ loss, const float* __restrict__ acc, float* __restrict__ out)
{
    __shared__ float rl[1024], ra[1024];
    int t = threadIdx.x;
    float s = 0.f, a = 0.f;
    for (int i = t; i < B; i += 1024) { s += loss[i]; a += acc[i]; }
    rl[t] = s; ra[t] = a;
    __syncthreads();
    for (int off = 512; off; off >>= 1) {
        if (t < off) { rl[t] += rl[t + off]; ra[t] += ra[t + off]; }
        __syncthreads();
    }
    if (t == 0) { out[0] = rl[0] / (float)B; out[1] = ra[0] / (float)B; }
}

__global__ void write_m(const int* __restrict__ m, float* __restrict__ out)
{
    int idx = blockIdx.x * blockDim.x + threadIdx.x;
    if (idx < B * LP1) out[2 + idx] = (float)m[idx];
}

__global__ void write_wc(const float* __restrict__ wcnt, float* __restrict__ out)
{
    int v = blockIdx.x * blockDim.x + threadIdx.x;
    if (v < V) out[2 + B * LP1 + v] = wcnt[v];
}

// ================= launch =================
extern "C" void kernel_launch(void* const* d_in, const int* in_sizes, int n_in,
                              void* d_out, int out_size)
{
    const float* target = (const float*)d_in[0];
    const float* dis    = (const float*)d_in[1];
    const float* wcin   = (const float*)d_in[2];
    const float* emb_s  = (const float*)d_in[3];
    const float* affsW  = (const float*)d_in[4];
    const float* affsb  = (const float*)d_in[5];
    const float* Wih    = (const float*)d_in[6];
    const float* Whh    = (const float*)d_in[7];
    const float* bih    = (const float*)d_in[8];
    const float* bhh    = (const float*)d_in[9];
    const float* lpW    = (const float*)d_in[10];
    const float* lpb    = (const float*)d_in[11];
    const float* emb_r  = (const float*)d_in[12];
    const float* rWih   = (const float*)d_in[13];
    const float* rWhh   = (const float*)d_in[14];
    const float* rbih   = (const float*)d_in[15];
    const float* rbhh   = (const float*)d_in[16];
    const float* affrW  = (const float*)d_in[17];
    const float* affrb  = (const float*)d_in[18];
    float* out = (float*)d_out;

    cudaFuncSetAttribute(hmma3<3>, cudaFuncAttributeMaxDynamicSharedMemorySize, DSM_BYTES);
    cudaFuncSetAttribute(hmma3<1>, cudaFuncAttributeMaxDynamicSharedMemorySize, DSM_NP1);

    float *p_c, *p_gates, *p_scores, *p_vl, *p_nwc, *p_r, *p_loss, *p_acc, *p_wcnt;
    float *p_bc, *p_bcR, *p_Ts, *p_Tr;
    int *p_tok, *p_sl, *p_m;
    __half *h0[2], *h1[2], *W0p, *W1p, *R0p, *R1p, *L0p, *L1p, *S0p, *S1p, *A0p, *A1p;
    __half *T0p, *T1p, *E0p, *E1p, *Fe0p, *Fe1p;
    cudaGetSymbolAddress((void**)&p_c, g_c);
    cudaGetSymbolAddress((void**)&p_gates, g_gates);
    cudaGetSymbolAddress((void**)&p_scores, g_scores);
    cudaGetSymbolAddress((void**)&p_vl, g_vl);
    cudaGetSymbolAddress((void**)&p_nwc, g_nwc);
    cudaGetSymbolAddress((void**)&p_r, g_r);
    cudaGetSymbolAddress((void**)&p_loss, g_loss);
    cudaGetSymbolAddress((void**)&p_acc, g_acc);
    cudaGetSymbolAddress((void**)&p_wcnt, g_wcnt);
    cudaGetSymbolAddress((void**)&p_bc, g_bc);
    cudaGetSymbolAddress((void**)&p_bcR, g_bcR);
    cudaGetSymbolAddress((void**)&p_Ts, g_Ts);
    cudaGetSymbolAddress((void**)&p_Tr, g_Tr);
    cudaGetSymbolAddress((void**)&p_tok, g_tok);
    cudaGetSymbolAddress((void**)&p_sl, g_sl);
    cudaGetSymbolAddress((void**)&p_m, g_m);
    cudaGetSymbolAddress((void**)&h0[0], g_h0a); cudaGetSymbolAddress((void**)&h1[0], g_h1a);
    cudaGetSymbolAddress((void**)&h0[1], g_h0b); cudaGetSymbolAddress((void**)&h1[1], g_h1b);
    cudaGetSymbolAddress((void**)&W0p, g_W0p);  cudaGetSymbolAddress((void**)&W1p, g_W1p);
    cudaGetSymbolAddress((void**)&R0p, g_R0p);  cudaGetSymbolAddress((void**)&R1p, g_R1p);
    cudaGetSymbolAddress((void**)&L0p, g_L0p);  cudaGetSymbolAddress((void**)&L1p, g_L1p);
    cudaGetSymbolAddress((void**)&S0p, g_S0p);  cudaGetSymbolAddress((void**)&S1p, g_S1p);
    cudaGetSymbolAddress((void**)&A0p, g_A0p);  cudaGetSymbolAddress((void**)&A1p, g_A1p);
    cudaGetSymbolAddress((void**)&T0p, g_T0p);  cudaGetSymbolAddress((void**)&T1p, g_T1p);
    cudaGetSymbolAddress((void**)&E0p, g_E0p);  cudaGetSymbolAddress((void**)&E1p, g_E1p);
    cudaGetSymbolAddress((void**)&Fe0p, g_F0p); cudaGetSymbolAddress((void**)&Fe1p, g_F1p);

    const int BH = B * H;

    // ---- setup ----
    build_nwc<<<1, 1024>>>(wcin, p_nwc);
    bias_int<<<(G4H + 255) / 256, 256>>>(bih, bhh, p_bc);
    bias_int<<<(G4H + 255) / 256, 256>>>(rbih, rbhh, p_bcR);
    build_wc_int<<<(G4H * KC + 255) / 256, 256>>>(Wih, Whh, W0p, W1p);
    build_wc_int<<<(G4H * KC + 255) / 256, 256>>>(rWih, rWhh, R0p, R1p);
    split2_kernel<<<(V * H + 255) / 256, 256>>>(lpW, V * H, L0p, L1p);
    split2_kernel<<<(H * F + 255) / 256, 256>>>(affsW, H * F, S0p, S1p);
    split2_kernel<<<(F * H + 255) / 256, 256>>>(affrW, F * H, A0p, A1p);
    split2_kernel<<<(B * F + 255) / 256, 256>>>(target, B * F, T0p, T1p);
    split2_kernel<<<(V * E + 255) / 256, 256>>>(emb_s, V * E, E0p, E1p);
    split2_kernel<<<(V * E + 255) / 256, 256>>>(emb_r, V * E, Fe0p, Fe1p);
    zero_f<<<(BH + 255) / 256, 256>>>(p_c, BH);
    init_sender<<<(B + 255) / 256, 256>>>(p_tok, p_sl, p_vl, p_m);

    // ---- token tables (fp32-accurate; cheap) ----
    hmma3<3><<<dim3(G4H / 128, V / 128), 512, DSM_BYTES>>>(
        E0p, E1p, E, W0p, W1p, KC, p_Ts, G4H, p_bc, E,
        0, nullptr, 0, nullptr, nullptr, nullptr, nullptr);
    hmma3<3><<<dim3(G4H / 128, V / 128), 512, DSM_BYTES>>>(
        Fe0p, Fe1p, E, R0p, R1p, KC, p_Tr, G4H, p_bcR, E,
        0, nullptr, 0, nullptr, nullptr, nullptr, nullptr);

    // ---- h0 = target @ aff_s_W^T + aff_s_b (token-critical: fp32-equivalent) ----
    hmma3<3><<<dim3(H / 128, B / 128), 512, DSM_BYTES>>>(
        T0p, T1p, F, S0p, S1p, F, p_gates, H, affsb, F,
        0, nullptr, 0, nullptr, nullptr, nullptr, nullptr);
    h_split2<<<(BH + 255) / 256, 256>>>(p_gates, h0[0], h1[0]);

    // ---- sender loop (token-critical: fp32-equivalent split-2) ----
    int cur = 0;
    for (int i = 0; i < L; i++) {
        hmma3<3><<<dim3(G4H / 128, B / 128), 512, DSM_BYTES>>>(
            h0[cur], h1[cur], H, W0p + E, W1p + E, KC, nullptr, 0, nullptr, H,
            1, p_tok, 1, p_Ts, p_c, h0[cur ^ 1], h1[cur ^ 1]);
        cur ^= 1;
        hmma3<3><<<dim3(V / 128, B / 128), 512, DSM_BYTES>>>(
            h0[cur], h1[cur], H, L0p, L1p, H, p_scores, V, lpb, H,
            0, nullptr, 0, nullptr, nullptr, nullptr, nullptr);
        score_step<<<B, 256>>>(p_scores, p_nwc, p_tok, p_sl, p_vl, p_m, i);
    }

    pad_m<<<(B * LP1 + 255) / 256, 256>>>(p_m, p_sl);
    zero_f<<<(V + 255) / 256, 256>>>(p_wcnt, V);
    hist_m<<<(B * LP1 + 255) / 256, 256>>>(p_m, p_wcnt);

    // ---- receiver (loss-only: single-pass fp16) ----
    zero_f<<<(BH + 255) / 256, 256>>>(p_c, BH);
    zero_h2<<<(BH + 255) / 256, 256>>>(h0[cur], h1[cur], BH);
    for (int t = 0; t < LP1; t++) {
        hmma3<1><<<dim3(G4H / 128, B / 128), 512, DSM_NP1>>>(
            h0[cur], h1[cur], H, R0p + E, R1p + E, KC, nullptr, 0, nullptr, H,
            1, p_m + t, LP1, p_Tr, p_c, h0[cur ^ 1], h1[cur ^ 1]);
        cur ^= 1;
    }

    // ---- r = hr @ aff_r_W^T + aff_r_b (loss-only: single-pass fp16) ----
    hmma3<1><<<dim3(F / 128, B / 128), 512, DSM_NP1>>>(
        h0[cur], h1[cur], H, A0p, A1p, H, p_r, F, affrb, H,
        0, nullptr, 0, nullptr, nullptr, nullptr, nullptr);

    hinge_kernel<<<B, 256>>>(target, dis, p_r, p_vl, p_loss, p_acc);
    finalize<<<1, 1024>>>(p_loss, p_acc, out);
    write_m<<<(B * LP1 + 255) / 256, 256>>>(p_m, out);
    write_wc<<<(V + 255) / 256, 256>>>(p_wcnt, out);
}